// round 8
// baseline (speedup 1.0000x reference)
#include <cuda_runtime.h>
#include <math.h>

#define NN 100000
#define DD 128
#define ND (NN * DD)
#define EMAX 1600000
#define NPART 782           // ceil(100000 / 128)

// ---------------- scratch (allocation-free: __device__ globals) ----------------
__device__ int    g_deg[2][NN];
__device__ float  g_norm[2][NN];
__device__ int    g_rowptr[2][NN + 1];
__device__ int    g_cursor[2][NN];
__device__ int    g_part[2][NPART];
__device__ int    g_col[2][EMAX];        // src ids grouped by dst
__device__ float  g_buf[2][2][ND];       // ping-pong feature buffers per graph
__device__ double g_sum[2][DD];
__device__ double g_sumsq[2][DD];
__device__ float  g_mean[2][DD];
__device__ float  g_inv[2][DD];

// ---------------- init: zero deg + stats ----------------
__global__ void k_init(int g) {
    int idx = blockIdx.x * blockDim.x + threadIdx.x;
    int stride = gridDim.x * blockDim.x;
    for (int i = idx; i < NN; i += stride) g_deg[g][i] = 0;
    if (idx < DD) { g_sum[g][idx] = 0.0; g_sumsq[g][idx] = 0.0; }
}

// ---------------- degree histogram ----------------
__global__ void k_count(int g, const int* __restrict__ dst, int E) {
    int i = blockIdx.x * blockDim.x + threadIdx.x;
    if (i < E) atomicAdd(&g_deg[g][dst[i]], 1);
}

// ---------------- scan stage 1: per-block (128 elems) partial sums ----------------
__global__ void __launch_bounds__(128) k_scan1(int g) {
    __shared__ int wsum[4];
    int t = threadIdx.x;
    int i = blockIdx.x * 128 + t;
    int v = (i < NN) ? g_deg[g][i] : 0;
    int x = v;
    for (int o = 16; o > 0; o >>= 1) x += __shfl_down_sync(0xffffffffu, x, o);
    if ((t & 31) == 0) wsum[t >> 5] = x;
    __syncthreads();
    if (t == 0) g_part[g][blockIdx.x] = wsum[0] + wsum[1] + wsum[2] + wsum[3];
}

// ---------------- scan stage 2: exclusive scan of NPART partials (1 block) -------
__global__ void __launch_bounds__(1024) k_scan2(int g) {
    __shared__ int sm[1024];
    int t = threadIdx.x;
    sm[t] = (t < NPART) ? g_part[g][t] : 0;
    __syncthreads();
    for (int off = 1; off < 1024; off <<= 1) {
        int v = sm[t];
        int add = (t >= off) ? sm[t - off] : 0;
        __syncthreads();
        sm[t] = v + add;
        __syncthreads();
    }
    if (t < NPART) g_part[g][t] = (t == 0) ? 0 : sm[t - 1];
    if (t == 0) g_rowptr[g][NN] = sm[NPART - 1];
}

// ---------------- scan stage 3: block-local scan + offset; also compute norm -----
__global__ void __launch_bounds__(128) k_scan3(int g) {
    __shared__ int wsum[4], woff[4];
    int t = threadIdx.x;
    int lane = t & 31, wid = t >> 5;
    int i = blockIdx.x * 128 + t;
    int v = (i < NN) ? g_deg[g][i] : 0;
    int x = v;
    for (int o = 1; o < 32; o <<= 1) {
        int y = __shfl_up_sync(0xffffffffu, x, o);
        if (lane >= o) x += y;
    }
    if (lane == 31) wsum[wid] = x;
    __syncthreads();
    if (t == 0) {
        int r = 0;
        for (int k = 0; k < 4; k++) { woff[k] = r; r += wsum[k]; }
    }
    __syncthreads();
    int excl = x - v + woff[wid] + g_part[g][blockIdx.x];
    if (i < NN) {
        g_rowptr[g][i] = excl;
        g_cursor[g][i] = excl;
        g_norm[g][i] = rsqrtf(fmaxf((float)v, 1.f));
    }
}

// ---------------- CSR fill: col grouped by dst ----------------
__global__ void k_fill(int g, const int* __restrict__ src, const int* __restrict__ dst, int E) {
    int i = blockIdx.x * blockDim.x + threadIdx.x;
    if (i < E) {
        int pos = atomicAdd(&g_cursor[g][dst[i]], 1);
        g_col[g][pos] = src[i];
    }
}

// ---------------- fused gather + GCNII layer (reads src_feat, writes dst_feat) --
__global__ void __launch_bounds__(256) k_layer(int g, const float* __restrict__ src_feat,
                                               float* __restrict__ dst_feat,
                                               const float* __restrict__ feat0,
                                               const float* __restrict__ W,
                                               const float* __restrict__ bias, float beta) {
    __shared__ float hs[64][DD];   // 32 KB
    int row0 = blockIdx.x * 64;
    int w = threadIdx.x >> 5, lane = threadIdx.x & 31;

    const float4* feat4 = reinterpret_cast<const float4*>(src_feat);
    const float4* f04 = reinterpret_cast<const float4*>(feat0);
    const int* __restrict__ rp = g_rowptr[g];
    const int* __restrict__ col = g_col[g];
    const float* __restrict__ nrm = g_norm[g];

    // ---- gather phase: warp w handles rows [8w, 8w+8), 4 edges in flight ----
    for (int r8 = 0; r8 < 8; r8++) {
        int r = w * 8 + r8;
        int n = row0 + r;
        float4 acc = make_float4(0.f, 0.f, 0.f, 0.f);
        if (n < NN) {
            int beg = __ldg(&rp[n]);
            int end = __ldg(&rp[n + 1]);
            int e = beg;
            for (; e + 3 < end; e += 4) {
                int s0 = __ldg(&col[e]);
                int s1 = __ldg(&col[e + 1]);
                int s2 = __ldg(&col[e + 2]);
                int s3 = __ldg(&col[e + 3]);
                float c0 = __ldg(&nrm[s0]);
                float c1 = __ldg(&nrm[s1]);
                float c2 = __ldg(&nrm[s2]);
                float c3 = __ldg(&nrm[s3]);
                float4 v0 = feat4[(size_t)s0 * 32 + lane];
                float4 v1 = feat4[(size_t)s1 * 32 + lane];
                float4 v2 = feat4[(size_t)s2 * 32 + lane];
                float4 v3 = feat4[(size_t)s3 * 32 + lane];
                acc.x += v0.x * c0 + v1.x * c1 + v2.x * c2 + v3.x * c3;
                acc.y += v0.y * c0 + v1.y * c1 + v2.y * c2 + v3.y * c3;
                acc.z += v0.z * c0 + v1.z * c1 + v2.z * c2 + v3.z * c3;
                acc.w += v0.w * c0 + v1.w * c1 + v2.w * c2 + v3.w * c3;
            }
            for (; e < end; e++) {
                int s0 = __ldg(&col[e]);
                float c0 = __ldg(&nrm[s0]);
                float4 v0 = feat4[(size_t)s0 * 32 + lane];
                acc.x += v0.x * c0;
                acc.y += v0.y * c0;
                acc.z += v0.z * c0;
                acc.w += v0.w * c0;
            }
            float nr = nrm[n];
            float4 f = f04[(size_t)n * 32 + lane];
            acc.x = 0.9f * acc.x * nr + 0.1f * f.x;
            acc.y = 0.9f * acc.y * nr + 0.1f * f.y;
            acc.z = 0.9f * acc.z * nr + 0.1f * f.z;
            acc.w = 0.9f * acc.w * nr + 0.1f * f.w;
        }
        reinterpret_cast<float4*>(&hs[r][0])[lane] = acc;
    }
    __syncthreads();

    float acc[8][4];
#pragma unroll
    for (int r = 0; r < 8; r++)
#pragma unroll
        for (int j = 0; j < 4; j++) acc[r][j] = 0.f;

#pragma unroll 4
    for (int k = 0; k < DD; k++) {
        float wv0 = __ldg(&W[k * DD + lane]);
        float wv1 = __ldg(&W[k * DD + lane + 32]);
        float wv2 = __ldg(&W[k * DD + lane + 64]);
        float wv3 = __ldg(&W[k * DD + lane + 96]);
#pragma unroll
        for (int r = 0; r < 8; r++) {
            float hv = hs[w * 8 + r][k];
            acc[r][0] = fmaf(hv, wv0, acc[r][0]);
            acc[r][1] = fmaf(hv, wv1, acc[r][1]);
            acc[r][2] = fmaf(hv, wv2, acc[r][2]);
            acc[r][3] = fmaf(hv, wv3, acc[r][3]);
        }
    }

    float ob = 1.f - beta;
#pragma unroll
    for (int r = 0; r < 8; r++) {
        int n = row0 + w * 8 + r;
        if (n >= NN) continue;
#pragma unroll
        for (int j = 0; j < 4; j++) {
            int c = lane + 32 * j;
            float h = hs[w * 8 + r][c];
            float o = ob * h + beta * acc[r][j] + __ldg(&bias[c]);
            dst_feat[(size_t)n * DD + c] = fmaxf(o, 0.f);
        }
    }
}

// ---------------- per-column stats (sum, sumsq) ----------------
__global__ void k_stats(int g, const float* __restrict__ feat) {
    __shared__ float ssum[256], ssq[256];
    int c = threadIdx.x & 127;
    int half = threadIdx.x >> 7;
    int row0 = blockIdx.x * 256;
    int rend = row0 + 256;
    if (rend > NN) rend = NN;
    float s = 0.f, q = 0.f;
    for (int r = row0 + half; r < rend; r += 2) {
        float v = feat[(size_t)r * DD + c];
        s += v;
        q += v * v;
    }
    ssum[threadIdx.x] = s;
    ssq[threadIdx.x] = q;
    __syncthreads();
    if (half == 0) {
        double ts = (double)ssum[c] + (double)ssum[c + 128];
        double tq = (double)ssq[c] + (double)ssq[c + 128];
        atomicAdd(&g_sum[g][c], ts);
        atomicAdd(&g_sumsq[g][c], tq);
    }
}

__global__ void k_finalize(int g) {
    int c = threadIdx.x;
    if (c < DD) {
        double mean = g_sum[g][c] / (double)NN;
        double var = (g_sumsq[g][c] - (double)NN * mean * mean) / (double)(NN - 1);
        if (var < 0.0) var = 0.0;
        float sd = (float)sqrt(var);
        g_mean[g][c] = (float)mean;
        g_inv[g][c] = 1.f / fmaxf(sd, 1e-12f);
    }
}

__global__ void k_write(int g, const float* __restrict__ feat, float* __restrict__ out) {
    int idx = blockIdx.x * blockDim.x + threadIdx.x;
    int stride = gridDim.x * blockDim.x;
    for (int i = idx; i < ND; i += stride) {
        int c = i & 127;
        out[i] = (feat[i] - g_mean[g][c]) * g_inv[g][c];
    }
}

// ---------------- launch (single stream — capture-safe) ----------------
extern "C" void kernel_launch(void* const* d_in, const int* in_sizes, int n_in,
                              void* d_out, int out_size) {
    const float* feat[2] = {(const float*)d_in[0], (const float*)d_in[1]};
    const int* srcs[2] = {(const int*)d_in[2], (const int*)d_in[4]};
    const int* dsts[2] = {(const int*)d_in[3], (const int*)d_in[5]};
    const float* weights = (const float*)d_in[6];
    const float* biases = (const float*)d_in[7];
    int E = in_sizes[2];
    float* out = (float*)d_out;

    static float* buf_addr[2][2] = {{nullptr, nullptr}, {nullptr, nullptr}};
    if (!buf_addr[0][0]) {
        void* p = nullptr;
        cudaGetSymbolAddress(&p, g_buf);
        float* base = (float*)p;
        for (int g = 0; g < 2; g++)
            for (int b = 0; b < 2; b++)
                buf_addr[g][b] = base + ((size_t)g * 2 + b) * (size_t)ND;
    }

    int eb = (E + 255) / 256;
    int layer_blocks = (NN + 63) / 64;
    int stats_blocks = (NN + 255) / 256;

    for (int g = 0; g < 2; g++) {
        k_init<<<256, 256>>>(g);
        k_count<<<eb, 256>>>(g, dsts[g], E);
        k_scan1<<<NPART, 128>>>(g);
        k_scan2<<<1, 1024>>>(g);
        k_scan3<<<NPART, 128>>>(g);
        k_fill<<<eb, 256>>>(g, srcs[g], dsts[g], E);
        for (int l = 0; l < 4; l++) {
            float beta = logf(1.0f / (float)(l + 1) + 1.0f);
            const float* sf = (l == 0) ? feat[g] : buf_addr[g][(l - 1) & 1];
            float* df = buf_addr[g][l & 1];
            k_layer<<<layer_blocks, 256>>>(g, sf, df, feat[g],
                                           weights + (size_t)l * DD * DD,
                                           biases + (size_t)l * DD, beta);
        }
        const float* fin = buf_addr[g][1];   // layer 3 writes buf[1]
        k_stats<<<stats_blocks, 256>>>(g, fin);
        k_finalize<<<1, DD>>>(g);
        k_write<<<1024, 256>>>(g, fin, out + (size_t)g * ND);
    }
}

// round 9
// speedup vs baseline: 1.0926x; 1.0926x over previous
#include <cuda_runtime.h>
#include <math.h>

#define NN 100000
#define DD 128
#define ND (NN * DD)
#define EMAX 1600000
#define NPART 782           // ceil(100000 / 128)

// ---------------- scratch (allocation-free: __device__ globals) ----------------
__device__ int    g_deg[2][NN];
__device__ float  g_norm[2][NN];
__device__ int    g_rowptr[2][NN + 1];
__device__ int    g_cursor[2][NN];
__device__ int    g_part[2][NPART];
__device__ int    g_col[2][EMAX];        // src ids grouped by dst
__device__ float  g_buf[2][2][ND];       // ping-pong feature buffers per graph
__device__ double g_sum[2][DD];
__device__ double g_sumsq[2][DD];
__device__ float  g_mean[2][DD];
__device__ float  g_inv[2][DD];

// ---------------- init: zero deg + stats (both graphs, blockIdx.y = g) ----------
__global__ void k_init() {
    int g = blockIdx.y;
    int idx = blockIdx.x * blockDim.x + threadIdx.x;
    int stride = gridDim.x * blockDim.x;
    for (int i = idx; i < NN; i += stride) g_deg[g][i] = 0;
    if (idx < DD) { g_sum[g][idx] = 0.0; g_sumsq[g][idx] = 0.0; }
}

// ---------------- degree histogram (both graphs) ----------------
__global__ void k_count(const int* __restrict__ dst0, const int* __restrict__ dst1, int E) {
    int g = blockIdx.y;
    const int* dst = g ? dst1 : dst0;
    int i = blockIdx.x * blockDim.x + threadIdx.x;
    if (i < E) atomicAdd(&g_deg[g][dst[i]], 1);
}

// ---------------- scan stage 1: per-block (128 elems) partial sums ----------------
__global__ void __launch_bounds__(128) k_scan1() {
    int g = blockIdx.y;
    __shared__ int wsum[4];
    int t = threadIdx.x;
    int i = blockIdx.x * 128 + t;
    int v = (i < NN) ? g_deg[g][i] : 0;
    int x = v;
    for (int o = 16; o > 0; o >>= 1) x += __shfl_down_sync(0xffffffffu, x, o);
    if ((t & 31) == 0) wsum[t >> 5] = x;
    __syncthreads();
    if (t == 0) g_part[g][blockIdx.x] = wsum[0] + wsum[1] + wsum[2] + wsum[3];
}

// ---------------- scan stage 2: exclusive scan of NPART partials (1 block/graph) -
__global__ void __launch_bounds__(1024) k_scan2() {
    int g = blockIdx.y;
    __shared__ int sm[1024];
    int t = threadIdx.x;
    sm[t] = (t < NPART) ? g_part[g][t] : 0;
    __syncthreads();
    for (int off = 1; off < 1024; off <<= 1) {
        int v = sm[t];
        int add = (t >= off) ? sm[t - off] : 0;
        __syncthreads();
        sm[t] = v + add;
        __syncthreads();
    }
    if (t < NPART) g_part[g][t] = (t == 0) ? 0 : sm[t - 1];
    if (t == 0) g_rowptr[g][NN] = sm[NPART - 1];
}

// ---------------- scan stage 3: block-local scan + offset; also compute norm -----
__global__ void __launch_bounds__(128) k_scan3() {
    int g = blockIdx.y;
    __shared__ int wsum[4], woff[4];
    int t = threadIdx.x;
    int lane = t & 31, wid = t >> 5;
    int i = blockIdx.x * 128 + t;
    int v = (i < NN) ? g_deg[g][i] : 0;
    int x = v;
    for (int o = 1; o < 32; o <<= 1) {
        int y = __shfl_up_sync(0xffffffffu, x, o);
        if (lane >= o) x += y;
    }
    if (lane == 31) wsum[wid] = x;
    __syncthreads();
    if (t == 0) {
        int r = 0;
        for (int k = 0; k < 4; k++) { woff[k] = r; r += wsum[k]; }
    }
    __syncthreads();
    int excl = x - v + woff[wid] + g_part[g][blockIdx.x];
    if (i < NN) {
        g_rowptr[g][i] = excl;
        g_cursor[g][i] = excl;
        g_norm[g][i] = rsqrtf(fmaxf((float)v, 1.f));
    }
}

// ---------------- CSR fill: col grouped by dst (both graphs) ----------------
__global__ void k_fill(const int* __restrict__ src0, const int* __restrict__ dst0,
                       const int* __restrict__ src1, const int* __restrict__ dst1, int E) {
    int g = blockIdx.y;
    const int* src = g ? src1 : src0;
    const int* dst = g ? dst1 : dst0;
    int i = blockIdx.x * blockDim.x + threadIdx.x;
    if (i < E) {
        int pos = atomicAdd(&g_cursor[g][dst[i]], 1);
        g_col[g][pos] = src[i];
    }
}

// ---------------- fused gather + GCNII layer, both graphs (blockIdx.y = g) -------
__global__ void __launch_bounds__(256) k_layer(const float* __restrict__ sf0,
                                               const float* __restrict__ sf1,
                                               float* __restrict__ df0,
                                               float* __restrict__ df1,
                                               const float* __restrict__ f00,
                                               const float* __restrict__ f01,
                                               const float* __restrict__ W,
                                               const float* __restrict__ bias, float beta) {
    __shared__ float hs[64][DD];   // 32 KB
    int g = blockIdx.y;
    const float* src_feat = g ? sf1 : sf0;
    float* dst_feat = g ? df1 : df0;
    const float* feat0 = g ? f01 : f00;

    int row0 = blockIdx.x * 64;
    int w = threadIdx.x >> 5, lane = threadIdx.x & 31;

    const float4* feat4 = reinterpret_cast<const float4*>(src_feat);
    const float4* f04 = reinterpret_cast<const float4*>(feat0);
    const int* __restrict__ rp = g_rowptr[g];
    const int* __restrict__ col = g_col[g];
    const float* __restrict__ nrm = g_norm[g];

    for (int r8 = 0; r8 < 8; r8++) {
        int r = w * 8 + r8;
        int n = row0 + r;
        float4 acc = make_float4(0.f, 0.f, 0.f, 0.f);
        if (n < NN) {
            int beg = __ldg(&rp[n]);
            int end = __ldg(&rp[n + 1]);
            int e = beg;
            for (; e + 1 < end; e += 2) {
                int s0 = __ldg(&col[e]);
                int s1 = __ldg(&col[e + 1]);
                float c0 = __ldg(&nrm[s0]);
                float c1 = __ldg(&nrm[s1]);
                float4 v0 = feat4[(size_t)s0 * 32 + lane];
                float4 v1 = feat4[(size_t)s1 * 32 + lane];
                acc.x += v0.x * c0 + v1.x * c1;
                acc.y += v0.y * c0 + v1.y * c1;
                acc.z += v0.z * c0 + v1.z * c1;
                acc.w += v0.w * c0 + v1.w * c1;
            }
            if (e < end) {
                int s0 = __ldg(&col[e]);
                float c0 = __ldg(&nrm[s0]);
                float4 v0 = feat4[(size_t)s0 * 32 + lane];
                acc.x += v0.x * c0;
                acc.y += v0.y * c0;
                acc.z += v0.z * c0;
                acc.w += v0.w * c0;
            }
            float nr = nrm[n];
            float4 f = f04[(size_t)n * 32 + lane];
            acc.x = 0.9f * acc.x * nr + 0.1f * f.x;
            acc.y = 0.9f * acc.y * nr + 0.1f * f.y;
            acc.z = 0.9f * acc.z * nr + 0.1f * f.z;
            acc.w = 0.9f * acc.w * nr + 0.1f * f.w;
        }
        reinterpret_cast<float4*>(&hs[r][0])[lane] = acc;
    }
    __syncthreads();

    float acc[8][4];
#pragma unroll
    for (int r = 0; r < 8; r++)
#pragma unroll
        for (int j = 0; j < 4; j++) acc[r][j] = 0.f;

#pragma unroll 4
    for (int k = 0; k < DD; k++) {
        float wv0 = __ldg(&W[k * DD + lane]);
        float wv1 = __ldg(&W[k * DD + lane + 32]);
        float wv2 = __ldg(&W[k * DD + lane + 64]);
        float wv3 = __ldg(&W[k * DD + lane + 96]);
#pragma unroll
        for (int r = 0; r < 8; r++) {
            float hv = hs[w * 8 + r][k];
            acc[r][0] = fmaf(hv, wv0, acc[r][0]);
            acc[r][1] = fmaf(hv, wv1, acc[r][1]);
            acc[r][2] = fmaf(hv, wv2, acc[r][2]);
            acc[r][3] = fmaf(hv, wv3, acc[r][3]);
        }
    }

    float ob = 1.f - beta;
#pragma unroll
    for (int r = 0; r < 8; r++) {
        int n = row0 + w * 8 + r;
        if (n >= NN) continue;
#pragma unroll
        for (int j = 0; j < 4; j++) {
            int c = lane + 32 * j;
            float h = hs[w * 8 + r][c];
            float o = ob * h + beta * acc[r][j] + __ldg(&bias[c]);
            dst_feat[(size_t)n * DD + c] = fmaxf(o, 0.f);
        }
    }
}

// ---------------- per-column stats (sum, sumsq), both graphs ----------------
__global__ void k_stats(const float* __restrict__ feat0, const float* __restrict__ feat1) {
    int g = blockIdx.y;
    const float* feat = g ? feat1 : feat0;
    __shared__ float ssum[256], ssq[256];
    int c = threadIdx.x & 127;
    int half = threadIdx.x >> 7;
    int row0 = blockIdx.x * 256;
    int rend = row0 + 256;
    if (rend > NN) rend = NN;
    float s = 0.f, q = 0.f;
    for (int r = row0 + half; r < rend; r += 2) {
        float v = feat[(size_t)r * DD + c];
        s += v;
        q += v * v;
    }
    ssum[threadIdx.x] = s;
    ssq[threadIdx.x] = q;
    __syncthreads();
    if (half == 0) {
        double ts = (double)ssum[c] + (double)ssum[c + 128];
        double tq = (double)ssq[c] + (double)ssq[c + 128];
        atomicAdd(&g_sum[g][c], ts);
        atomicAdd(&g_sumsq[g][c], tq);
    }
}

__global__ void k_finalize() {
    int g = blockIdx.y;
    int c = threadIdx.x;
    if (c < DD) {
        double mean = g_sum[g][c] / (double)NN;
        double var = (g_sumsq[g][c] - (double)NN * mean * mean) / (double)(NN - 1);
        if (var < 0.0) var = 0.0;
        float sd = (float)sqrt(var);
        g_mean[g][c] = (float)mean;
        g_inv[g][c] = 1.f / fmaxf(sd, 1e-12f);
    }
}

__global__ void k_write(const float* __restrict__ feat0, const float* __restrict__ feat1,
                        float* __restrict__ out) {
    int g = blockIdx.y;
    const float* feat = g ? feat1 : feat0;
    float* o = out + (size_t)g * ND;
    int idx = blockIdx.x * blockDim.x + threadIdx.x;
    int stride = gridDim.x * blockDim.x;
    for (int i = idx; i < ND; i += stride) {
        int c = i & 127;
        o[i] = (feat[i] - g_mean[g][c]) * g_inv[g][c];
    }
}

// ---------------- launch (single stream — capture-safe) ----------------
extern "C" void kernel_launch(void* const* d_in, const int* in_sizes, int n_in,
                              void* d_out, int out_size) {
    const float* feat0 = (const float*)d_in[0];
    const float* feat1 = (const float*)d_in[1];
    const int* src0 = (const int*)d_in[2];
    const int* dst0 = (const int*)d_in[3];
    const int* src1 = (const int*)d_in[4];
    const int* dst1 = (const int*)d_in[5];
    const float* weights = (const float*)d_in[6];
    const float* biases = (const float*)d_in[7];
    int E = in_sizes[2];
    float* out = (float*)d_out;

    static float* buf_addr[2][2] = {{nullptr, nullptr}, {nullptr, nullptr}};
    if (!buf_addr[0][0]) {
        void* p = nullptr;
        cudaGetSymbolAddress(&p, g_buf);
        float* base = (float*)p;
        for (int g = 0; g < 2; g++)
            for (int b = 0; b < 2; b++)
                buf_addr[g][b] = base + ((size_t)g * 2 + b) * (size_t)ND;
    }

    int eb = (E + 255) / 256;
    int layer_blocks = (NN + 63) / 64;
    int stats_blocks = (NN + 255) / 256;

    k_init<<<dim3(256, 2), 256>>>();
    k_count<<<dim3(eb, 2), 256>>>(dst0, dst1, E);
    k_scan1<<<dim3(NPART, 2), 128>>>();
    k_scan2<<<dim3(1, 2), 1024>>>();
    k_scan3<<<dim3(NPART, 2), 128>>>();
    k_fill<<<dim3(eb, 2), 256>>>(src0, dst0, src1, dst1, E);

    for (int l = 0; l < 4; l++) {
        float beta = logf(1.0f / (float)(l + 1) + 1.0f);
        const float* sf0 = (l == 0) ? feat0 : buf_addr[0][(l - 1) & 1];
        const float* sf1 = (l == 0) ? feat1 : buf_addr[1][(l - 1) & 1];
        float* df0 = buf_addr[0][l & 1];
        float* df1 = buf_addr[1][l & 1];
        k_layer<<<dim3(layer_blocks, 2), 256>>>(sf0, sf1, df0, df1, feat0, feat1,
                                                weights + (size_t)l * DD * DD,
                                                biases + (size_t)l * DD, beta);
    }

    const float* fin0 = buf_addr[0][1];   // layer 3 writes buf[1]
    const float* fin1 = buf_addr[1][1];
    k_stats<<<dim3(stats_blocks, 2), 256>>>(fin0, fin1);
    k_finalize<<<dim3(1, 2), DD>>>();
    k_write<<<dim3(1024, 2), 256>>>(fin0, fin1, out);
}

// round 11
// speedup vs baseline: 1.2067x; 1.1044x over previous
#include <cuda_runtime.h>
#include <cuda_fp16.h>
#include <math.h>

#define NN 100000
#define DD 128
#define ND (NN * DD)
#define EMAX 1600000
#define NPART 782           // ceil(100000 / 128)

// ---------------- scratch (allocation-free: __device__ globals) ----------------
__device__ int    g_deg[2][NN];
__device__ float  g_norm[2][NN];
__device__ int    g_rowptr[2][NN + 1];
__device__ int    g_cursor[2][NN];
__device__ int    g_part[2][NPART];
__device__ int    g_col[2][EMAX];        // src ids grouped by dst
__device__ __half g_h16[2][2][ND];       // fp16 ping-pong gather buffers per graph
__device__ float  g_fin[2][ND];          // fp32 final layer output per graph
__device__ double g_sum[2][DD];
__device__ double g_sumsq[2][DD];
__device__ float  g_mean[2][DD];
__device__ float  g_inv[2][DD];

// ---------------- init: zero deg + stats (both graphs, blockIdx.y = g) ----------
__global__ void k_init() {
    int g = blockIdx.y;
    int idx = blockIdx.x * blockDim.x + threadIdx.x;
    int stride = gridDim.x * blockDim.x;
    for (int i = idx; i < NN; i += stride) g_deg[g][i] = 0;
    if (idx < DD) { g_sum[g][idx] = 0.0; g_sumsq[g][idx] = 0.0; }
}

// ---------------- degree histogram (both graphs) ----------------
__global__ void k_count(const int* __restrict__ dst0, const int* __restrict__ dst1, int E) {
    int g = blockIdx.y;
    const int* dst = g ? dst1 : dst0;
    int i = blockIdx.x * blockDim.x + threadIdx.x;
    if (i < E) atomicAdd(&g_deg[g][dst[i]], 1);
}

// ---------------- convert input features to fp16 (both graphs) ----------------
__global__ void k_tofp16(const float* __restrict__ f0, const float* __restrict__ f1) {
    int g = blockIdx.y;
    const float4* src = reinterpret_cast<const float4*>(g ? f1 : f0);
    uint2* dst = reinterpret_cast<uint2*>(g_h16[g][0]);
    int idx = blockIdx.x * blockDim.x + threadIdx.x;
    int stride = gridDim.x * blockDim.x;
    for (int i = idx; i < ND / 4; i += stride) {
        float4 v = src[i];
        __half2 lo = __floats2half2_rn(v.x, v.y);
        __half2 hi = __floats2half2_rn(v.z, v.w);
        uint2 o;
        o.x = *reinterpret_cast<unsigned*>(&lo);
        o.y = *reinterpret_cast<unsigned*>(&hi);
        dst[i] = o;
    }
}

// ---------------- scan stage 1: per-block (128 elems) partial sums ----------------
__global__ void __launch_bounds__(128) k_scan1() {
    int g = blockIdx.y;
    __shared__ int wsum[4];
    int t = threadIdx.x;
    int i = blockIdx.x * 128 + t;
    int v = (i < NN) ? g_deg[g][i] : 0;
    int x = v;
    for (int o = 16; o > 0; o >>= 1) x += __shfl_down_sync(0xffffffffu, x, o);
    if ((t & 31) == 0) wsum[t >> 5] = x;
    __syncthreads();
    if (t == 0) g_part[g][blockIdx.x] = wsum[0] + wsum[1] + wsum[2] + wsum[3];
}

// ---------------- scan stage 2: exclusive scan of NPART partials (1 block/graph) -
__global__ void __launch_bounds__(1024) k_scan2() {
    int g = blockIdx.y;
    __shared__ int sm[1024];
    int t = threadIdx.x;
    sm[t] = (t < NPART) ? g_part[g][t] : 0;
    __syncthreads();
    for (int off = 1; off < 1024; off <<= 1) {
        int v = sm[t];
        int add = (t >= off) ? sm[t - off] : 0;
        __syncthreads();
        sm[t] = v + add;
        __syncthreads();
    }
    if (t < NPART) g_part[g][t] = (t == 0) ? 0 : sm[t - 1];
    if (t == 0) g_rowptr[g][NN] = sm[NPART - 1];
}

// ---------------- scan stage 3: block-local scan + offset; also compute norm -----
__global__ void __launch_bounds__(128) k_scan3() {
    int g = blockIdx.y;
    __shared__ int wsum[4], woff[4];
    int t = threadIdx.x;
    int lane = t & 31, wid = t >> 5;
    int i = blockIdx.x * 128 + t;
    int v = (i < NN) ? g_deg[g][i] : 0;
    int x = v;
    for (int o = 1; o < 32; o <<= 1) {
        int y = __shfl_up_sync(0xffffffffu, x, o);
        if (lane >= o) x += y;
    }
    if (lane == 31) wsum[wid] = x;
    __syncthreads();
    if (t == 0) {
        int r = 0;
        for (int k = 0; k < 4; k++) { woff[k] = r; r += wsum[k]; }
    }
    __syncthreads();
    int excl = x - v + woff[wid] + g_part[g][blockIdx.x];
    if (i < NN) {
        g_rowptr[g][i] = excl;
        g_cursor[g][i] = excl;
        g_norm[g][i] = rsqrtf(fmaxf((float)v, 1.f));
    }
}

// ---------------- CSR fill: col grouped by dst (both graphs) ----------------
__global__ void k_fill(const int* __restrict__ src0, const int* __restrict__ dst0,
                       const int* __restrict__ src1, const int* __restrict__ dst1, int E) {
    int g = blockIdx.y;
    const int* src = g ? src1 : src0;
    const int* dst = g ? dst1 : dst0;
    int i = blockIdx.x * blockDim.x + threadIdx.x;
    if (i < E) {
        int pos = atomicAdd(&g_cursor[g][dst[i]], 1);
        g_col[g][pos] = src[i];
    }
}

// ---------------- fused gather(fp16) + GCNII layer, both graphs -------------------
// gather reads fp16 rows (8 B/lane), accumulates fp32; GEMM fp32;
// epilogue writes fp16 (layers 0-2) or fp32 (layer 3).
__global__ void __launch_bounds__(256) k_layer(const __half* __restrict__ s16_0,
                                               const __half* __restrict__ s16_1,
                                               __half* __restrict__ dh0,
                                               __half* __restrict__ dh1,
                                               float* __restrict__ df0,
                                               float* __restrict__ df1,
                                               const float* __restrict__ f00,
                                               const float* __restrict__ f01,
                                               const float* __restrict__ W,
                                               const float* __restrict__ bias,
                                               float beta, int is_last) {
    __shared__ float hs[64][DD];   // 32 KB
    int g = blockIdx.y;
    const uint2* feat8 = reinterpret_cast<const uint2*>(g ? s16_1 : s16_0);
    const float4* f04 = reinterpret_cast<const float4*>(g ? f01 : f00);
    __half* dsth = g ? dh1 : dh0;
    float* dstf = g ? df1 : df0;

    int row0 = blockIdx.x * 64;
    int w = threadIdx.x >> 5, lane = threadIdx.x & 31;

    const int* __restrict__ rp = g_rowptr[g];
    const int* __restrict__ col = g_col[g];
    const float* __restrict__ nrm = g_norm[g];

    for (int r8 = 0; r8 < 8; r8++) {
        int r = w * 8 + r8;
        int n = row0 + r;
        float4 acc = make_float4(0.f, 0.f, 0.f, 0.f);
        if (n < NN) {
            int beg = __ldg(&rp[n]);
            int end = __ldg(&rp[n + 1]);
            int e = beg;
            for (; e + 1 < end; e += 2) {
                int s0 = __ldg(&col[e]);
                int s1 = __ldg(&col[e + 1]);
                float c0 = __ldg(&nrm[s0]);
                float c1 = __ldg(&nrm[s1]);
                uint2 u0 = feat8[(size_t)s0 * 32 + lane];
                uint2 u1 = feat8[(size_t)s1 * 32 + lane];
                float2 a0 = __half22float2(*reinterpret_cast<__half2*>(&u0.x));
                float2 b0 = __half22float2(*reinterpret_cast<__half2*>(&u0.y));
                float2 a1 = __half22float2(*reinterpret_cast<__half2*>(&u1.x));
                float2 b1 = __half22float2(*reinterpret_cast<__half2*>(&u1.y));
                acc.x += a0.x * c0 + a1.x * c1;
                acc.y += a0.y * c0 + a1.y * c1;
                acc.z += b0.x * c0 + b1.x * c1;
                acc.w += b0.y * c0 + b1.y * c1;
            }
            if (e < end) {
                int s0 = __ldg(&col[e]);
                float c0 = __ldg(&nrm[s0]);
                uint2 u0 = feat8[(size_t)s0 * 32 + lane];
                float2 a0 = __half22float2(*reinterpret_cast<__half2*>(&u0.x));
                float2 b0 = __half22float2(*reinterpret_cast<__half2*>(&u0.y));
                acc.x += a0.x * c0;
                acc.y += a0.y * c0;
                acc.z += b0.x * c0;
                acc.w += b0.y * c0;
            }
            float nr = nrm[n];
            float4 f = f04[(size_t)n * 32 + lane];
            acc.x = 0.9f * acc.x * nr + 0.1f * f.x;
            acc.y = 0.9f * acc.y * nr + 0.1f * f.y;
            acc.z = 0.9f * acc.z * nr + 0.1f * f.z;
            acc.w = 0.9f * acc.w * nr + 0.1f * f.w;
        }
        reinterpret_cast<float4*>(&hs[r][0])[lane] = acc;
    }
    __syncthreads();

    float acc[8][4];
#pragma unroll
    for (int r = 0; r < 8; r++)
#pragma unroll
        for (int j = 0; j < 4; j++) acc[r][j] = 0.f;

#pragma unroll 4
    for (int k = 0; k < DD; k++) {
        float wv0 = __ldg(&W[k * DD + lane]);
        float wv1 = __ldg(&W[k * DD + lane + 32]);
        float wv2 = __ldg(&W[k * DD + lane + 64]);
        float wv3 = __ldg(&W[k * DD + lane + 96]);
#pragma unroll
        for (int r = 0; r < 8; r++) {
            float hv = hs[w * 8 + r][k];
            acc[r][0] = fmaf(hv, wv0, acc[r][0]);
            acc[r][1] = fmaf(hv, wv1, acc[r][1]);
            acc[r][2] = fmaf(hv, wv2, acc[r][2]);
            acc[r][3] = fmaf(hv, wv3, acc[r][3]);
        }
    }

    float ob = 1.f - beta;
#pragma unroll
    for (int r = 0; r < 8; r++) {
        int n = row0 + w * 8 + r;
        if (n >= NN) continue;
#pragma unroll
        for (int j = 0; j < 4; j++) {
            int c = lane + 32 * j;
            float h = hs[w * 8 + r][c];
            float o = ob * h + beta * acc[r][j] + __ldg(&bias[c]);
            o = fmaxf(o, 0.f);
            if (is_last) dstf[(size_t)n * DD + c] = o;
            else         dsth[(size_t)n * DD + c] = __float2half_rn(o);
        }
    }
}

// ---------------- per-column stats (sum, sumsq), both graphs ----------------
__global__ void k_stats(const float* __restrict__ feat0, const float* __restrict__ feat1) {
    int g = blockIdx.y;
    const float* feat = g ? feat1 : feat0;
    __shared__ float ssum[256], ssq[256];
    int c = threadIdx.x & 127;
    int half = threadIdx.x >> 7;
    int row0 = blockIdx.x * 256;
    int rend = row0 + 256;
    if (rend > NN) rend = NN;
    float s = 0.f, q = 0.f;
    for (int r = row0 + half; r < rend; r += 2) {
        float v = feat[(size_t)r * DD + c];
        s += v;
        q += v * v;
    }
    ssum[threadIdx.x] = s;
    ssq[threadIdx.x] = q;
    __syncthreads();
    if (half == 0) {
        double ts = (double)ssum[c] + (double)ssum[c + 128];
        double tq = (double)ssq[c] + (double)ssq[c + 128];
        atomicAdd(&g_sum[g][c], ts);
        atomicAdd(&g_sumsq[g][c], tq);
    }
}

__global__ void k_finalize() {
    int g = blockIdx.y;
    int c = threadIdx.x;
    if (c < DD) {
        double mean = g_sum[g][c] / (double)NN;
        double var = (g_sumsq[g][c] - (double)NN * mean * mean) / (double)(NN - 1);
        if (var < 0.0) var = 0.0;
        float sd = (float)sqrt(var);
        g_mean[g][c] = (float)mean;
        g_inv[g][c] = 1.f / fmaxf(sd, 1e-12f);
    }
}

__global__ void k_write(const float* __restrict__ feat0, const float* __restrict__ feat1,
                        float* __restrict__ out) {
    int g = blockIdx.y;
    const float* feat = g ? feat1 : feat0;
    float* o = out + (size_t)g * ND;
    int idx = blockIdx.x * blockDim.x + threadIdx.x;
    int stride = gridDim.x * blockDim.x;
    for (int i = idx; i < ND; i += stride) {
        int c = i & 127;
        o[i] = (feat[i] - g_mean[g][c]) * g_inv[g][c];
    }
}

// ---------------- launch (single stream — capture-safe) ----------------
extern "C" void kernel_launch(void* const* d_in, const int* in_sizes, int n_in,
                              void* d_out, int out_size) {
    const float* feat0 = (const float*)d_in[0];
    const float* feat1 = (const float*)d_in[1];
    const int* src0 = (const int*)d_in[2];
    const int* dst0 = (const int*)d_in[3];
    const int* src1 = (const int*)d_in[4];
    const int* dst1 = (const int*)d_in[5];
    const float* weights = (const float*)d_in[6];
    const float* biases = (const float*)d_in[7];
    int E = in_sizes[2];
    float* out = (float*)d_out;

    static __half* h16_addr[2][2] = {{nullptr, nullptr}, {nullptr, nullptr}};
    static float* fin_addr[2] = {nullptr, nullptr};
    if (!h16_addr[0][0]) {
        void* p = nullptr;
        cudaGetSymbolAddress(&p, g_h16);
        __half* hbase = (__half*)p;
        for (int g = 0; g < 2; g++)
            for (int b = 0; b < 2; b++)
                h16_addr[g][b] = hbase + ((size_t)g * 2 + b) * (size_t)ND;
        cudaGetSymbolAddress(&p, g_fin);
        float* fbase = (float*)p;
        for (int g = 0; g < 2; g++) fin_addr[g] = fbase + (size_t)g * ND;
    }

    int eb = (E + 255) / 256;
    int layer_blocks = (NN + 63) / 64;
    int stats_blocks = (NN + 255) / 256;

    k_init<<<dim3(256, 2), 256>>>();
    k_count<<<dim3(eb, 2), 256>>>(dst0, dst1, E);
    k_tofp16<<<dim3(1024, 2), 256>>>(feat0, feat1);
    k_scan1<<<dim3(NPART, 2), 128>>>();
    k_scan2<<<dim3(1, 2), 1024>>>();
    k_scan3<<<dim3(NPART, 2), 128>>>();
    k_fill<<<dim3(eb, 2), 256>>>(src0, dst0, src1, dst1, E);

    // conversion wrote h16[g][0]; layer l reads h16[g][l&1], writes h16[g][(l+1)&1]
    // (layers 0-2); layer 3 reads h16[g][1], writes g_fin[g] in fp32.
    for (int l = 0; l < 4; l++) {
        float beta = logf(1.0f / (float)(l + 1) + 1.0f);
        int is_last = (l == 3) ? 1 : 0;
        const __half* s0 = h16_addr[0][l & 1];
        const __half* s1 = h16_addr[1][l & 1];
        __half* dh0 = h16_addr[0][(l + 1) & 1];
        __half* dh1 = h16_addr[1][(l + 1) & 1];
        k_layer<<<dim3(layer_blocks, 2), 256>>>(s0, s1, dh0, dh1,
                                                fin_addr[0], fin_addr[1],
                                                feat0, feat1,
                                                weights + (size_t)l * DD * DD,
                                                biases + (size_t)l * DD, beta, is_last);
    }

    k_stats<<<dim3(stats_blocks, 2), 256>>>(fin_addr[0], fin_addr[1]);
    k_finalize<<<dim3(1, 2), DD>>>();
    k_write<<<dim3(1024, 2), 256>>>(fin_addr[0], fin_addr[1], out);
}

// round 12
// speedup vs baseline: 1.4847x; 1.2304x over previous
#include <cuda_runtime.h>
#include <cuda_fp16.h>
#include <mma.h>
#include <math.h>

using namespace nvcuda;

#define NN 100000
#define DD 128
#define ND (NN * DD)
#define EMAX 1600000
#define NPART 782           // ceil(100000 / 128)

// ---------------- scratch (allocation-free: __device__ globals) ----------------
__device__ int    g_deg[2][NN];
__device__ float  g_norm[2][NN];
__device__ int    g_rowptr[2][NN + 1];
__device__ int    g_cursor[2][NN];
__device__ int    g_part[2][NPART];
__device__ int    g_col[2][EMAX];        // src ids grouped by dst
__device__ __half g_h16[2][2][ND];       // fp16 ping-pong gather buffers per graph
__device__ float  g_fin[2][ND];          // fp32 final layer output per graph
__device__ __half g_w16[4][DD * DD];     // folded fp16 weights: beta*W + (1-beta)*I
__device__ double g_sum[2][DD];
__device__ double g_sumsq[2][DD];
__device__ float  g_mean[2][DD];
__device__ float  g_inv[2][DD];

// ---------------- init: zero deg + stats (both graphs, blockIdx.y = g) ----------
__global__ void k_init() {
    int g = blockIdx.y;
    int idx = blockIdx.x * blockDim.x + threadIdx.x;
    int stride = gridDim.x * blockDim.x;
    for (int i = idx; i < NN; i += stride) g_deg[g][i] = 0;
    if (idx < DD) { g_sum[g][idx] = 0.0; g_sumsq[g][idx] = 0.0; }
}

// ---------------- degree histogram (both graphs) ----------------
__global__ void k_count(const int* __restrict__ dst0, const int* __restrict__ dst1, int E) {
    int g = blockIdx.y;
    const int* dst = g ? dst1 : dst0;
    int i = blockIdx.x * blockDim.x + threadIdx.x;
    if (i < E) atomicAdd(&g_deg[g][dst[i]], 1);
}

// ---------------- convert input features to fp16 (both graphs) ----------------
__global__ void k_tofp16(const float* __restrict__ f0, const float* __restrict__ f1) {
    int g = blockIdx.y;
    const float4* src = reinterpret_cast<const float4*>(g ? f1 : f0);
    uint2* dst = reinterpret_cast<uint2*>(g_h16[g][0]);
    int idx = blockIdx.x * blockDim.x + threadIdx.x;
    int stride = gridDim.x * blockDim.x;
    for (int i = idx; i < ND / 4; i += stride) {
        float4 v = src[i];
        __half2 lo = __floats2half2_rn(v.x, v.y);
        __half2 hi = __floats2half2_rn(v.z, v.w);
        uint2 o;
        o.x = *reinterpret_cast<unsigned*>(&lo);
        o.y = *reinterpret_cast<unsigned*>(&hi);
        dst[i] = o;
    }
}

// ---------------- fold weights: W'[l] = beta_l * W[l] + (1-beta_l) * I, fp16 -----
__global__ void k_wfold(const float* __restrict__ W) {
    int l = blockIdx.y;
    float beta = logf(1.0f / (float)(l + 1) + 1.0f);
    int idx = blockIdx.x * blockDim.x + threadIdx.x;   // 0 .. 16383
    int k = idx >> 7, n = idx & 127;
    float v = beta * W[(size_t)l * DD * DD + idx];
    if (k == n) v += 1.0f - beta;
    g_w16[l][idx] = __float2half_rn(v);
}

// ---------------- scan stage 1: per-block (128 elems) partial sums ----------------
__global__ void __launch_bounds__(128) k_scan1() {
    int g = blockIdx.y;
    __shared__ int wsum[4];
    int t = threadIdx.x;
    int i = blockIdx.x * 128 + t;
    int v = (i < NN) ? g_deg[g][i] : 0;
    int x = v;
    for (int o = 16; o > 0; o >>= 1) x += __shfl_down_sync(0xffffffffu, x, o);
    if ((t & 31) == 0) wsum[t >> 5] = x;
    __syncthreads();
    if (t == 0) g_part[g][blockIdx.x] = wsum[0] + wsum[1] + wsum[2] + wsum[3];
}

// ---------------- scan stage 2: exclusive scan of NPART partials (1 block/graph) -
__global__ void __launch_bounds__(1024) k_scan2() {
    int g = blockIdx.y;
    __shared__ int sm[1024];
    int t = threadIdx.x;
    sm[t] = (t < NPART) ? g_part[g][t] : 0;
    __syncthreads();
    for (int off = 1; off < 1024; off <<= 1) {
        int v = sm[t];
        int add = (t >= off) ? sm[t - off] : 0;
        __syncthreads();
        sm[t] = v + add;
        __syncthreads();
    }
    if (t < NPART) g_part[g][t] = (t == 0) ? 0 : sm[t - 1];
    if (t == 0) g_rowptr[g][NN] = sm[NPART - 1];
}

// ---------------- scan stage 3: block-local scan + offset; also compute norm -----
__global__ void __launch_bounds__(128) k_scan3() {
    int g = blockIdx.y;
    __shared__ int wsum[4], woff[4];
    int t = threadIdx.x;
    int lane = t & 31, wid = t >> 5;
    int i = blockIdx.x * 128 + t;
    int v = (i < NN) ? g_deg[g][i] : 0;
    int x = v;
    for (int o = 1; o < 32; o <<= 1) {
        int y = __shfl_up_sync(0xffffffffu, x, o);
        if (lane >= o) x += y;
    }
    if (lane == 31) wsum[wid] = x;
    __syncthreads();
    if (t == 0) {
        int r = 0;
        for (int k = 0; k < 4; k++) { woff[k] = r; r += wsum[k]; }
    }
    __syncthreads();
    int excl = x - v + woff[wid] + g_part[g][blockIdx.x];
    if (i < NN) {
        g_rowptr[g][i] = excl;
        g_cursor[g][i] = excl;
        g_norm[g][i] = rsqrtf(fmaxf((float)v, 1.f));
    }
}

// ---------------- CSR fill: col grouped by dst (both graphs) ----------------
__global__ void k_fill(const int* __restrict__ src0, const int* __restrict__ dst0,
                       const int* __restrict__ src1, const int* __restrict__ dst1, int E) {
    int g = blockIdx.y;
    const int* src = g ? src1 : src0;
    const int* dst = g ? dst1 : dst0;
    int i = blockIdx.x * blockDim.x + threadIdx.x;
    if (i < E) {
        int pos = atomicAdd(&g_cursor[g][dst[i]], 1);
        g_col[g][pos] = src[i];
    }
}

// ---------------- fused gather(fp16) + wmma GEMM layer, both graphs ---------------
// h = 0.9*agg*norm + 0.1*feat0 written fp16 to smem; out = relu(h @ W' + bias)
// where W' = beta*W + (1-beta)*I (identity-folded, fp16 in global/L1).
// smem: 32 KB block, first 16 KB = fp16 h tile during gather+MMA, then reused
// as fp32 [64][128] staging for the MMA result during the epilogue.
__global__ void __launch_bounds__(256) k_layer(const __half* __restrict__ s16_0,
                                               const __half* __restrict__ s16_1,
                                               __half* __restrict__ dh0,
                                               __half* __restrict__ dh1,
                                               float* __restrict__ df0,
                                               float* __restrict__ df1,
                                               const float* __restrict__ f00,
                                               const float* __restrict__ f01,
                                               const __half* __restrict__ Wf,
                                               const float* __restrict__ bias,
                                               int is_last) {
    __shared__ __align__(16) unsigned char smem_raw[64 * DD * 4];  // 32 KB
    __half* hs16 = reinterpret_cast<__half*>(smem_raw);            // [64][128] fp16
    float* outs = reinterpret_cast<float*>(smem_raw);              // [64][128] fp32

    int g = blockIdx.y;
    const uint2* feat8 = reinterpret_cast<const uint2*>(g ? s16_1 : s16_0);
    const float4* f04 = reinterpret_cast<const float4*>(g ? f01 : f00);
    __half* dsth = g ? dh1 : dh0;
    float* dstf = g ? df1 : df0;

    int row0 = blockIdx.x * 64;
    int w = threadIdx.x >> 5, lane = threadIdx.x & 31;

    const int* __restrict__ rp = g_rowptr[g];
    const int* __restrict__ col = g_col[g];
    const float* __restrict__ nrm = g_norm[g];

    // ---- gather phase: warp w handles rows [8w, 8w+8) ----
    for (int r8 = 0; r8 < 8; r8++) {
        int r = w * 8 + r8;
        int n = row0 + r;
        float4 acc = make_float4(0.f, 0.f, 0.f, 0.f);
        if (n < NN) {
            int beg = __ldg(&rp[n]);
            int end = __ldg(&rp[n + 1]);
            int e = beg;
            for (; e + 1 < end; e += 2) {
                int s0 = __ldg(&col[e]);
                int s1 = __ldg(&col[e + 1]);
                float c0 = __ldg(&nrm[s0]);
                float c1 = __ldg(&nrm[s1]);
                uint2 u0 = feat8[(size_t)s0 * 32 + lane];
                uint2 u1 = feat8[(size_t)s1 * 32 + lane];
                float2 a0 = __half22float2(*reinterpret_cast<__half2*>(&u0.x));
                float2 b0 = __half22float2(*reinterpret_cast<__half2*>(&u0.y));
                float2 a1 = __half22float2(*reinterpret_cast<__half2*>(&u1.x));
                float2 b1 = __half22float2(*reinterpret_cast<__half2*>(&u1.y));
                acc.x += a0.x * c0 + a1.x * c1;
                acc.y += a0.y * c0 + a1.y * c1;
                acc.z += b0.x * c0 + b1.x * c1;
                acc.w += b0.y * c0 + b1.y * c1;
            }
            if (e < end) {
                int s0 = __ldg(&col[e]);
                float c0 = __ldg(&nrm[s0]);
                uint2 u0 = feat8[(size_t)s0 * 32 + lane];
                float2 a0 = __half22float2(*reinterpret_cast<__half2*>(&u0.x));
                float2 b0 = __half22float2(*reinterpret_cast<__half2*>(&u0.y));
                acc.x += a0.x * c0;
                acc.y += a0.y * c0;
                acc.z += b0.x * c0;
                acc.w += b0.y * c0;
            }
            float nr = nrm[n];
            float4 f = f04[(size_t)n * 32 + lane];
            acc.x = 0.9f * acc.x * nr + 0.1f * f.x;
            acc.y = 0.9f * acc.y * nr + 0.1f * f.y;
            acc.z = 0.9f * acc.z * nr + 0.1f * f.z;
            acc.w = 0.9f * acc.w * nr + 0.1f * f.w;
        }
        // write h as fp16 (4 halfs = 8 bytes per lane)
        __half2 lo = __floats2half2_rn(acc.x, acc.y);
        __half2 hi = __floats2half2_rn(acc.z, acc.w);
        uint2 o;
        o.x = *reinterpret_cast<unsigned*>(&lo);
        o.y = *reinterpret_cast<unsigned*>(&hi);
        reinterpret_cast<uint2*>(&hs16[r * DD])[lane] = o;
    }
    __syncthreads();

    // ---- wmma phase: warp w -> row tile (w>>1)*16, col half (w&1)*64 ----
    {
        int rt = w >> 1;             // 0..3  -> rows rt*16 .. +16
        int ch = w & 1;              // 0..1  -> cols ch*64 .. +64
        wmma::fragment<wmma::accumulator, 16, 16, 16, float> fc[4];
#pragma unroll
        for (int ct = 0; ct < 4; ct++) wmma::fill_fragment(fc[ct], 0.f);

#pragma unroll
        for (int k0 = 0; k0 < 8; k0++) {
            wmma::fragment<wmma::matrix_a, 16, 16, 16, __half, wmma::row_major> fa;
            wmma::load_matrix_sync(fa, &hs16[(rt * 16) * DD + k0 * 16], DD);
#pragma unroll
            for (int ct = 0; ct < 4; ct++) {
                wmma::fragment<wmma::matrix_b, 16, 16, 16, __half, wmma::row_major> fb;
                wmma::load_matrix_sync(fb, &Wf[(k0 * 16) * DD + ch * 64 + ct * 16], DD);
                wmma::mma_sync(fc[ct], fa, fb, fc[ct]);
            }
        }
        __syncthreads();   // all frag_a loads done; safe to overwrite smem as fp32
#pragma unroll
        for (int ct = 0; ct < 4; ct++)
            wmma::store_matrix_sync(&outs[(rt * 16) * DD + ch * 64 + ct * 16], fc[ct],
                                    DD, wmma::mem_row_major);
    }
    __syncthreads();

    // ---- epilogue: o = relu(outs + bias); write fp16 (layers 0-2) or fp32 (3) ----
#pragma unroll
    for (int r8 = 0; r8 < 8; r8++) {
        int r = w * 8 + r8;
        int n = row0 + r;
        if (n >= NN) continue;
#pragma unroll
        for (int j = 0; j < 4; j++) {
            int c = lane + 32 * j;
            float o = outs[r * DD + c] + __ldg(&bias[c]);
            o = fmaxf(o, 0.f);
            if (is_last) dstf[(size_t)n * DD + c] = o;
            else         dsth[(size_t)n * DD + c] = __float2half_rn(o);
        }
    }
}

// ---------------- per-column stats (sum, sumsq), both graphs ----------------
__global__ void k_stats(const float* __restrict__ feat0, const float* __restrict__ feat1) {
    int g = blockIdx.y;
    const float* feat = g ? feat1 : feat0;
    __shared__ float ssum[256], ssq[256];
    int c = threadIdx.x & 127;
    int half = threadIdx.x >> 7;
    int row0 = blockIdx.x * 256;
    int rend = row0 + 256;
    if (rend > NN) rend = NN;
    float s = 0.f, q = 0.f;
    for (int r = row0 + half; r < rend; r += 2) {
        float v = feat[(size_t)r * DD + c];
        s += v;
        q += v * v;
    }
    ssum[threadIdx.x] = s;
    ssq[threadIdx.x] = q;
    __syncthreads();
    if (half == 0) {
        double ts = (double)ssum[c] + (double)ssum[c + 128];
        double tq = (double)ssq[c] + (double)ssq[c + 128];
        atomicAdd(&g_sum[g][c], ts);
        atomicAdd(&g_sumsq[g][c], tq);
    }
}

__global__ void k_finalize() {
    int g = blockIdx.y;
    int c = threadIdx.x;
    if (c < DD) {
        double mean = g_sum[g][c] / (double)NN;
        double var = (g_sumsq[g][c] - (double)NN * mean * mean) / (double)(NN - 1);
        if (var < 0.0) var = 0.0;
        float sd = (float)sqrt(var);
        g_mean[g][c] = (float)mean;
        g_inv[g][c] = 1.f / fmaxf(sd, 1e-12f);
    }
}

__global__ void k_write(const float* __restrict__ feat0, const float* __restrict__ feat1,
                        float* __restrict__ out) {
    int g = blockIdx.y;
    const float* feat = g ? feat1 : feat0;
    float* o = out + (size_t)g * ND;
    int idx = blockIdx.x * blockDim.x + threadIdx.x;
    int stride = gridDim.x * blockDim.x;
    for (int i = idx; i < ND; i += stride) {
        int c = i & 127;
        o[i] = (feat[i] - g_mean[g][c]) * g_inv[g][c];
    }
}

// ---------------- launch (single stream — capture-safe) ----------------
extern "C" void kernel_launch(void* const* d_in, const int* in_sizes, int n_in,
                              void* d_out, int out_size) {
    const float* feat0 = (const float*)d_in[0];
    const float* feat1 = (const float*)d_in[1];
    const int* src0 = (const int*)d_in[2];
    const int* dst0 = (const int*)d_in[3];
    const int* src1 = (const int*)d_in[4];
    const int* dst1 = (const int*)d_in[5];
    const float* weights = (const float*)d_in[6];
    const float* biases = (const float*)d_in[7];
    int E = in_sizes[2];
    float* out = (float*)d_out;

    static __half* h16_addr[2][2] = {{nullptr, nullptr}, {nullptr, nullptr}};
    static float* fin_addr[2] = {nullptr, nullptr};
    static __half* w16_addr = nullptr;
    if (!h16_addr[0][0]) {
        void* p = nullptr;
        cudaGetSymbolAddress(&p, g_h16);
        __half* hbase = (__half*)p;
        for (int g = 0; g < 2; g++)
            for (int b = 0; b < 2; b++)
                h16_addr[g][b] = hbase + ((size_t)g * 2 + b) * (size_t)ND;
        cudaGetSymbolAddress(&p, g_fin);
        float* fbase = (float*)p;
        for (int g = 0; g < 2; g++) fin_addr[g] = fbase + (size_t)g * ND;
        cudaGetSymbolAddress(&p, g_w16);
        w16_addr = (__half*)p;
    }

    int eb = (E + 255) / 256;
    int layer_blocks = (NN + 63) / 64;
    int stats_blocks = (NN + 255) / 256;

    k_init<<<dim3(256, 2), 256>>>();
    k_count<<<dim3(eb, 2), 256>>>(dst0, dst1, E);
    k_tofp16<<<dim3(1024, 2), 256>>>(feat0, feat1);
    k_wfold<<<dim3(64, 4), 256>>>(weights);
    k_scan1<<<dim3(NPART, 2), 128>>>();
    k_scan2<<<dim3(1, 2), 1024>>>();
    k_scan3<<<dim3(NPART, 2), 128>>>();
    k_fill<<<dim3(eb, 2), 256>>>(src0, dst0, src1, dst1, E);

    // conversion wrote h16[g][0]; layer l reads h16[g][l&1], writes h16[g][(l+1)&1]
    // (layers 0-2); layer 3 reads h16[g][1], writes g_fin[g] in fp32.
    for (int l = 0; l < 4; l++) {
        int is_last = (l == 3) ? 1 : 0;
        const __half* s0 = h16_addr[0][l & 1];
        const __half* s1 = h16_addr[1][l & 1];
        __half* dh0 = h16_addr[0][(l + 1) & 1];
        __half* dh1 = h16_addr[1][(l + 1) & 1];
        k_layer<<<dim3(layer_blocks, 2), 256>>>(s0, s1, dh0, dh1,
                                                fin_addr[0], fin_addr[1],
                                                feat0, feat1,
                                                w16_addr + (size_t)l * DD * DD,
                                                biases + (size_t)l * DD, is_last);
    }

    k_stats<<<dim3(stats_blocks, 2), 256>>>(fin_addr[0], fin_addr[1]);
    k_finalize<<<dim3(1, 2), DD>>>();
    k_write<<<dim3(1024, 2), 256>>>(fin_addr[0], fin_addr[1], out);
}

// round 13
// speedup vs baseline: 1.4943x; 1.0065x over previous
#include <cuda_runtime.h>
#include <cuda_fp16.h>
#include <mma.h>
#include <math.h>

using namespace nvcuda;

#define NN 100000
#define DD 128
#define ND (NN * DD)
#define EMAX 1600000
#define NPART 782           // ceil(100000 / 128)

// ---------------- scratch (allocation-free: __device__ globals) ----------------
__device__ int    g_deg[2][NN];
__device__ float  g_norm[2][NN];
__device__ int    g_rowptr[2][NN + 1];
__device__ int    g_cursor[2][NN];
__device__ int    g_part[2][NPART];
__device__ int    g_col[2][EMAX];        // src ids grouped by dst
__device__ __half g_h16[2][2][ND];       // fp16 ping-pong gather buffers per graph
__device__ float  g_fin[2][ND];          // fp32 final layer output per graph
__device__ __half g_w16[4][DD * DD];     // folded fp16 weights: beta*W + (1-beta)*I
__device__ double g_sum[2][DD];
__device__ double g_sumsq[2][DD];
__device__ float  g_mean[2][DD];
__device__ float  g_inv[2][DD];

// ---------------- init: zero deg + stats (both graphs, blockIdx.y = g) ----------
__global__ void k_init() {
    int g = blockIdx.y;
    int idx = blockIdx.x * blockDim.x + threadIdx.x;
    int stride = gridDim.x * blockDim.x;
    for (int i = idx; i < NN; i += stride) g_deg[g][i] = 0;
    if (idx < DD) { g_sum[g][idx] = 0.0; g_sumsq[g][idx] = 0.0; }
}

// ---------------- degree histogram (both graphs) ----------------
__global__ void k_count(const int* __restrict__ dst0, const int* __restrict__ dst1, int E) {
    int g = blockIdx.y;
    const int* dst = g ? dst1 : dst0;
    int i = blockIdx.x * blockDim.x + threadIdx.x;
    if (i < E) atomicAdd(&g_deg[g][dst[i]], 1);
}

// ---------------- convert input features to fp16 (both graphs) ----------------
__global__ void k_tofp16(const float* __restrict__ f0, const float* __restrict__ f1) {
    int g = blockIdx.y;
    const float4* src = reinterpret_cast<const float4*>(g ? f1 : f0);
    uint2* dst = reinterpret_cast<uint2*>(g_h16[g][0]);
    int idx = blockIdx.x * blockDim.x + threadIdx.x;
    int stride = gridDim.x * blockDim.x;
    for (int i = idx; i < ND / 4; i += stride) {
        float4 v = src[i];
        __half2 lo = __floats2half2_rn(v.x, v.y);
        __half2 hi = __floats2half2_rn(v.z, v.w);
        uint2 o;
        o.x = *reinterpret_cast<unsigned*>(&lo);
        o.y = *reinterpret_cast<unsigned*>(&hi);
        dst[i] = o;
    }
}

// ---------------- fold weights: W'[l] = beta_l * W[l] + (1-beta_l) * I, fp16 -----
__global__ void k_wfold(const float* __restrict__ W) {
    int l = blockIdx.y;
    float beta = logf(1.0f / (float)(l + 1) + 1.0f);
    int idx = blockIdx.x * blockDim.x + threadIdx.x;   // 0 .. 16383
    int k = idx >> 7, n = idx & 127;
    float v = beta * W[(size_t)l * DD * DD + idx];
    if (k == n) v += 1.0f - beta;
    g_w16[l][idx] = __float2half_rn(v);
}

// ---------------- scan stage 1: per-block (128 elems) partial sums ----------------
__global__ void __launch_bounds__(128) k_scan1() {
    int g = blockIdx.y;
    __shared__ int wsum[4];
    int t = threadIdx.x;
    int i = blockIdx.x * 128 + t;
    int v = (i < NN) ? g_deg[g][i] : 0;
    int x = v;
    for (int o = 16; o > 0; o >>= 1) x += __shfl_down_sync(0xffffffffu, x, o);
    if ((t & 31) == 0) wsum[t >> 5] = x;
    __syncthreads();
    if (t == 0) g_part[g][blockIdx.x] = wsum[0] + wsum[1] + wsum[2] + wsum[3];
}

// ---------------- scan stage 2: exclusive scan of NPART partials (1 block/graph) -
__global__ void __launch_bounds__(1024) k_scan2() {
    int g = blockIdx.y;
    __shared__ int sm[1024];
    int t = threadIdx.x;
    sm[t] = (t < NPART) ? g_part[g][t] : 0;
    __syncthreads();
    for (int off = 1; off < 1024; off <<= 1) {
        int v = sm[t];
        int add = (t >= off) ? sm[t - off] : 0;
        __syncthreads();
        sm[t] = v + add;
        __syncthreads();
    }
    if (t < NPART) g_part[g][t] = (t == 0) ? 0 : sm[t - 1];
    if (t == 0) g_rowptr[g][NN] = sm[NPART - 1];
}

// ---------------- scan stage 3: block-local scan + offset; also compute norm -----
__global__ void __launch_bounds__(128) k_scan3() {
    int g = blockIdx.y;
    __shared__ int wsum[4], woff[4];
    int t = threadIdx.x;
    int lane = t & 31, wid = t >> 5;
    int i = blockIdx.x * 128 + t;
    int v = (i < NN) ? g_deg[g][i] : 0;
    int x = v;
    for (int o = 1; o < 32; o <<= 1) {
        int y = __shfl_up_sync(0xffffffffu, x, o);
        if (lane >= o) x += y;
    }
    if (lane == 31) wsum[wid] = x;
    __syncthreads();
    if (t == 0) {
        int r = 0;
        for (int k = 0; k < 4; k++) { woff[k] = r; r += wsum[k]; }
    }
    __syncthreads();
    int excl = x - v + woff[wid] + g_part[g][blockIdx.x];
    if (i < NN) {
        g_rowptr[g][i] = excl;
        g_cursor[g][i] = excl;
        g_norm[g][i] = rsqrtf(fmaxf((float)v, 1.f));
    }
}

// ---------------- CSR fill: col grouped by dst (both graphs) ----------------
__global__ void k_fill(const int* __restrict__ src0, const int* __restrict__ dst0,
                       const int* __restrict__ src1, const int* __restrict__ dst1, int E) {
    int g = blockIdx.y;
    const int* src = g ? src1 : src0;
    const int* dst = g ? dst1 : dst0;
    int i = blockIdx.x * blockDim.x + threadIdx.x;
    if (i < E) {
        int pos = atomicAdd(&g_cursor[g][dst[i]], 1);
        g_col[g][pos] = src[i];
    }
}

// ---------------- gather helpers ----------------
__device__ __forceinline__ void acc_edge(float4& acc, const uint2* feat8, int s,
                                         float c, int lane) {
    uint2 u = feat8[(size_t)s * 32 + lane];
    float2 a = __half22float2(*reinterpret_cast<__half2*>(&u.x));
    float2 b = __half22float2(*reinterpret_cast<__half2*>(&u.y));
    acc.x += a.x * c;
    acc.y += a.y * c;
    acc.z += b.x * c;
    acc.w += b.y * c;
}

// ---------------- fused gather(fp16) + wmma GEMM layer, both graphs ---------------
// h = 0.9*agg*norm + 0.1*feat0 written fp16 to smem; out = relu(h @ W' + bias)
// where W' = beta*W + (1-beta)*I. Layer 3 additionally accumulates column stats.
__global__ void __launch_bounds__(256) k_layer(const __half* __restrict__ s16_0,
                                               const __half* __restrict__ s16_1,
                                               __half* __restrict__ dh0,
                                               __half* __restrict__ dh1,
                                               float* __restrict__ df0,
                                               float* __restrict__ df1,
                                               const float* __restrict__ f00,
                                               const float* __restrict__ f01,
                                               const __half* __restrict__ Wf,
                                               const float* __restrict__ bias,
                                               int is_last) {
    __shared__ __align__(16) unsigned char smem_raw[64 * DD * 4];  // 32 KB
    __half* hs16 = reinterpret_cast<__half*>(smem_raw);            // [64][128] fp16
    float* outs = reinterpret_cast<float*>(smem_raw);              // [64][128] fp32

    int g = blockIdx.y;
    const uint2* feat8 = reinterpret_cast<const uint2*>(g ? s16_1 : s16_0);
    const float4* f04 = reinterpret_cast<const float4*>(g ? f01 : f00);
    __half* dsth = g ? dh1 : dh0;
    float* dstf = g ? df1 : df0;

    int row0 = blockIdx.x * 64;
    int tid = threadIdx.x;
    int w = tid >> 5, lane = tid & 31;

    const int* __restrict__ rp = g_rowptr[g];
    const int* __restrict__ col = g_col[g];
    const float* __restrict__ nrm = g_norm[g];

    // ---- gather phase: warp w handles rows [8w, 8w+8) as 4 interleaved pairs ----
    for (int pr = 0; pr < 4; pr++) {
        int rA = w * 8 + pr * 2;
        int rB = rA + 1;
        int nA = row0 + rA, nB = row0 + rB;
        float4 aA = make_float4(0.f, 0.f, 0.f, 0.f);
        float4 aB = make_float4(0.f, 0.f, 0.f, 0.f);
        int eA = 0, endA = 0, eB = 0, endB = 0;
        if (nA < NN) { eA = __ldg(&rp[nA]); endA = __ldg(&rp[nA + 1]); }
        if (nB < NN) { eB = __ldg(&rp[nB]); endB = __ldg(&rp[nB + 1]); }

        // paired main loop: 2 edges from each row in flight (4 feat loads)
        while (eA + 1 < endA && eB + 1 < endB) {
            int sA0 = __ldg(&col[eA]);
            int sA1 = __ldg(&col[eA + 1]);
            int sB0 = __ldg(&col[eB]);
            int sB1 = __ldg(&col[eB + 1]);
            float cA0 = __ldg(&nrm[sA0]);
            float cA1 = __ldg(&nrm[sA1]);
            float cB0 = __ldg(&nrm[sB0]);
            float cB1 = __ldg(&nrm[sB1]);
            acc_edge(aA, feat8, sA0, cA0, lane);
            acc_edge(aA, feat8, sA1, cA1, lane);
            acc_edge(aB, feat8, sB0, cB0, lane);
            acc_edge(aB, feat8, sB1, cB1, lane);
            eA += 2; eB += 2;
        }
        // tails
        for (; eA + 1 < endA; eA += 2) {
            int s0 = __ldg(&col[eA]);
            int s1 = __ldg(&col[eA + 1]);
            float c0 = __ldg(&nrm[s0]);
            float c1 = __ldg(&nrm[s1]);
            acc_edge(aA, feat8, s0, c0, lane);
            acc_edge(aA, feat8, s1, c1, lane);
        }
        if (eA < endA) {
            int s0 = __ldg(&col[eA]);
            acc_edge(aA, feat8, s0, __ldg(&nrm[s0]), lane);
        }
        for (; eB + 1 < endB; eB += 2) {
            int s0 = __ldg(&col[eB]);
            int s1 = __ldg(&col[eB + 1]);
            float c0 = __ldg(&nrm[s0]);
            float c1 = __ldg(&nrm[s1]);
            acc_edge(aB, feat8, s0, c0, lane);
            acc_edge(aB, feat8, s1, c1, lane);
        }
        if (eB < endB) {
            int s0 = __ldg(&col[eB]);
            acc_edge(aB, feat8, s0, __ldg(&nrm[s0]), lane);
        }

        // residual + store h as fp16
        if (nA < NN) {
            float nr = nrm[nA];
            float4 f = f04[(size_t)nA * 32 + lane];
            aA.x = 0.9f * aA.x * nr + 0.1f * f.x;
            aA.y = 0.9f * aA.y * nr + 0.1f * f.y;
            aA.z = 0.9f * aA.z * nr + 0.1f * f.z;
            aA.w = 0.9f * aA.w * nr + 0.1f * f.w;
        }
        if (nB < NN) {
            float nr = nrm[nB];
            float4 f = f04[(size_t)nB * 32 + lane];
            aB.x = 0.9f * aB.x * nr + 0.1f * f.x;
            aB.y = 0.9f * aB.y * nr + 0.1f * f.y;
            aB.z = 0.9f * aB.z * nr + 0.1f * f.z;
            aB.w = 0.9f * aB.w * nr + 0.1f * f.w;
        }
        {
            __half2 lo = __floats2half2_rn(aA.x, aA.y);
            __half2 hi = __floats2half2_rn(aA.z, aA.w);
            uint2 o;
            o.x = *reinterpret_cast<unsigned*>(&lo);
            o.y = *reinterpret_cast<unsigned*>(&hi);
            reinterpret_cast<uint2*>(&hs16[rA * DD])[lane] = o;
            lo = __floats2half2_rn(aB.x, aB.y);
            hi = __floats2half2_rn(aB.z, aB.w);
            o.x = *reinterpret_cast<unsigned*>(&lo);
            o.y = *reinterpret_cast<unsigned*>(&hi);
            reinterpret_cast<uint2*>(&hs16[rB * DD])[lane] = o;
        }
    }
    __syncthreads();

    // ---- wmma phase: warp w -> row tile (w>>1)*16, col half (w&1)*64 ----
    {
        int rt = w >> 1;
        int ch = w & 1;
        wmma::fragment<wmma::accumulator, 16, 16, 16, float> fc[4];
#pragma unroll
        for (int ct = 0; ct < 4; ct++) wmma::fill_fragment(fc[ct], 0.f);

#pragma unroll
        for (int k0 = 0; k0 < 8; k0++) {
            wmma::fragment<wmma::matrix_a, 16, 16, 16, __half, wmma::row_major> fa;
            wmma::load_matrix_sync(fa, &hs16[(rt * 16) * DD + k0 * 16], DD);
#pragma unroll
            for (int ct = 0; ct < 4; ct++) {
                wmma::fragment<wmma::matrix_b, 16, 16, 16, __half, wmma::row_major> fb;
                wmma::load_matrix_sync(fb, &Wf[(k0 * 16) * DD + ch * 64 + ct * 16], DD);
                wmma::mma_sync(fc[ct], fa, fb, fc[ct]);
            }
        }
        __syncthreads();   // all frag_a loads done; safe to overwrite smem as fp32
#pragma unroll
        for (int ct = 0; ct < 4; ct++)
            wmma::store_matrix_sync(&outs[(rt * 16) * DD + ch * 64 + ct * 16], fc[ct],
                                    DD, wmma::mem_row_major);
    }
    __syncthreads();

    // ---- epilogue: o = relu(outs + bias); column pairs (2*lane + 64j) ----
    float csum[4] = {0.f, 0.f, 0.f, 0.f};   // stats partials (layer 3 only)
    float csq[4] = {0.f, 0.f, 0.f, 0.f};
#pragma unroll
    for (int r8 = 0; r8 < 8; r8++) {
        int r = w * 8 + r8;
        int n = row0 + r;
        if (n >= NN) continue;
#pragma unroll
        for (int j = 0; j < 2; j++) {
            int c = 2 * lane + 64 * j;
            float o0 = outs[r * DD + c] + __ldg(&bias[c]);
            float o1 = outs[r * DD + c + 1] + __ldg(&bias[c + 1]);
            o0 = fmaxf(o0, 0.f);
            o1 = fmaxf(o1, 0.f);
            if (is_last) {
                dstf[(size_t)n * DD + c] = o0;
                dstf[(size_t)n * DD + c + 1] = o1;
                csum[2 * j] += o0;  csq[2 * j] += o0 * o0;
                csum[2 * j + 1] += o1;  csq[2 * j + 1] += o1 * o1;
            } else {
                __half2 h2 = __floats2half2_rn(o0, o1);
                *reinterpret_cast<__half2*>(&dsth[(size_t)n * DD + c]) = h2;
            }
        }
    }

    if (is_last) {
        __syncthreads();   // all reads of outs done
        float* red = outs; // reuse as [16][128]: rows 0-7 sum, 8-15 sumsq
#pragma unroll
        for (int j = 0; j < 2; j++) {
            red[w * DD + 2 * lane + 64 * j] = csum[2 * j];
            red[w * DD + 2 * lane + 64 * j + 1] = csum[2 * j + 1];
            red[(8 + w) * DD + 2 * lane + 64 * j] = csq[2 * j];
            red[(8 + w) * DD + 2 * lane + 64 * j + 1] = csq[2 * j + 1];
        }
        __syncthreads();
        int c = tid & 127;
        int which = tid >> 7;     // 0 = sum, 1 = sumsq
        float tot = 0.f;
#pragma unroll
        for (int w2 = 0; w2 < 8; w2++) tot += red[(which * 8 + w2) * DD + c];
        if (which == 0) atomicAdd(&g_sum[g][c], (double)tot);
        else            atomicAdd(&g_sumsq[g][c], (double)tot);
    }
}

__global__ void k_finalize() {
    int g = blockIdx.y;
    int c = threadIdx.x;
    if (c < DD) {
        double mean = g_sum[g][c] / (double)NN;
        double var = (g_sumsq[g][c] - (double)NN * mean * mean) / (double)(NN - 1);
        if (var < 0.0) var = 0.0;
        float sd = (float)sqrt(var);
        g_mean[g][c] = (float)mean;
        g_inv[g][c] = 1.f / fmaxf(sd, 1e-12f);
    }
}

__global__ void k_write(const float* __restrict__ feat0, const float* __restrict__ feat1,
                        float* __restrict__ out) {
    int g = blockIdx.y;
    const float* feat = g ? feat1 : feat0;
    float* o = out + (size_t)g * ND;
    int idx = blockIdx.x * blockDim.x + threadIdx.x;
    int stride = gridDim.x * blockDim.x;
    for (int i = idx; i < ND; i += stride) {
        int c = i & 127;
        o[i] = (feat[i] - g_mean[g][c]) * g_inv[g][c];
    }
}

// ---------------- launch (single stream — capture-safe) ----------------
extern "C" void kernel_launch(void* const* d_in, const int* in_sizes, int n_in,
                              void* d_out, int out_size) {
    const float* feat0 = (const float*)d_in[0];
    const float* feat1 = (const float*)d_in[1];
    const int* src0 = (const int*)d_in[2];
    const int* dst0 = (const int*)d_in[3];
    const int* src1 = (const int*)d_in[4];
    const int* dst1 = (const int*)d_in[5];
    const float* weights = (const float*)d_in[6];
    const float* biases = (const float*)d_in[7];
    int E = in_sizes[2];
    float* out = (float*)d_out;

    static __half* h16_addr[2][2] = {{nullptr, nullptr}, {nullptr, nullptr}};
    static float* fin_addr[2] = {nullptr, nullptr};
    static __half* w16_addr = nullptr;
    if (!h16_addr[0][0]) {
        void* p = nullptr;
        cudaGetSymbolAddress(&p, g_h16);
        __half* hbase = (__half*)p;
        for (int g = 0; g < 2; g++)
            for (int b = 0; b < 2; b++)
                h16_addr[g][b] = hbase + ((size_t)g * 2 + b) * (size_t)ND;
        cudaGetSymbolAddress(&p, g_fin);
        float* fbase = (float*)p;
        for (int g = 0; g < 2; g++) fin_addr[g] = fbase + (size_t)g * ND;
        cudaGetSymbolAddress(&p, g_w16);
        w16_addr = (__half*)p;
    }

    int eb = (E + 255) / 256;
    int layer_blocks = (NN + 63) / 64;

    k_init<<<dim3(256, 2), 256>>>();
    k_count<<<dim3(eb, 2), 256>>>(dst0, dst1, E);
    k_tofp16<<<dim3(1024, 2), 256>>>(feat0, feat1);
    k_wfold<<<dim3(64, 4), 256>>>(weights);
    k_scan1<<<dim3(NPART, 2), 128>>>();
    k_scan2<<<dim3(1, 2), 1024>>>();
    k_scan3<<<dim3(NPART, 2), 128>>>();
    k_fill<<<dim3(eb, 2), 256>>>(src0, dst0, src1, dst1, E);

    // conversion wrote h16[g][0]; layer l reads h16[g][l&1], writes h16[g][(l+1)&1]
    // (layers 0-2); layer 3 reads h16[g][1], writes g_fin[g] in fp32 + stats.
    for (int l = 0; l < 4; l++) {
        int is_last = (l == 3) ? 1 : 0;
        const __half* s0 = h16_addr[0][l & 1];
        const __half* s1 = h16_addr[1][l & 1];
        __half* dh0 = h16_addr[0][(l + 1) & 1];
        __half* dh1 = h16_addr[1][(l + 1) & 1];
        k_layer<<<dim3(layer_blocks, 2), 256>>>(s0, s1, dh0, dh1,
                                                fin_addr[0], fin_addr[1],
                                                feat0, feat1,
                                                w16_addr + (size_t)l * DD * DD,
                                                biases + (size_t)l * DD, is_last);
    }

    k_finalize<<<dim3(1, 2), DD>>>();
    k_write<<<dim3(1024, 2), 256>>>(fin_addr[0], fin_addr[1], out);
}

// round 14
// speedup vs baseline: 1.5239x; 1.0198x over previous
#include <cuda_runtime.h>
#include <cuda_fp16.h>
#include <mma.h>
#include <math.h>

using namespace nvcuda;

#define NN 100000
#define DD 128
#define ND (NN * DD)
#define EMAX 1600000
#define NPART 782           // ceil(100000 / 128)

// ---------------- scratch (allocation-free: __device__ globals) ----------------
__device__ int    g_deg[2][NN];
__device__ float  g_norm[2][NN];
__device__ int    g_rowptr[2][NN + 1];
__device__ int    g_cursor[2][NN];
__device__ int    g_part[2][NPART];
__device__ int    g_col[2][EMAX];        // src ids grouped by dst
__device__ __half g_h16[2][3][ND];       // buf0 = fp16(feat0) persistent; buf1/2 ping-pong
__device__ float  g_fin[2][ND];          // fp32 final layer output per graph
__device__ __half g_w16[4][DD * DD];     // folded fp16 weights: beta*W + (1-beta)*I
__device__ double g_sum[2][DD];
__device__ double g_sumsq[2][DD];
__device__ float  g_mean[2][DD];
__device__ float  g_inv[2][DD];

// ---------------- init: zero deg + stats (both graphs, blockIdx.y = g) ----------
__global__ void k_init() {
    int g = blockIdx.y;
    int idx = blockIdx.x * blockDim.x + threadIdx.x;
    int stride = gridDim.x * blockDim.x;
    for (int i = idx; i < NN; i += stride) g_deg[g][i] = 0;
    if (idx < DD) { g_sum[g][idx] = 0.0; g_sumsq[g][idx] = 0.0; }
}

// ---------------- degree histogram (both graphs) ----------------
__global__ void k_count(const int* __restrict__ dst0, const int* __restrict__ dst1, int E) {
    int g = blockIdx.y;
    const int* dst = g ? dst1 : dst0;
    int i = blockIdx.x * blockDim.x + threadIdx.x;
    if (i < E) atomicAdd(&g_deg[g][dst[i]], 1);
}

// ---------------- convert input features to fp16 (both graphs) -> buf0 ----------
__global__ void k_tofp16(const float* __restrict__ f0, const float* __restrict__ f1) {
    int g = blockIdx.y;
    const float4* src = reinterpret_cast<const float4*>(g ? f1 : f0);
    uint2* dst = reinterpret_cast<uint2*>(g_h16[g][0]);
    int idx = blockIdx.x * blockDim.x + threadIdx.x;
    int stride = gridDim.x * blockDim.x;
    for (int i = idx; i < ND / 4; i += stride) {
        float4 v = src[i];
        __half2 lo = __floats2half2_rn(v.x, v.y);
        __half2 hi = __floats2half2_rn(v.z, v.w);
        uint2 o;
        o.x = *reinterpret_cast<unsigned*>(&lo);
        o.y = *reinterpret_cast<unsigned*>(&hi);
        dst[i] = o;
    }
}

// ---------------- fold weights: W'[l] = beta_l * W[l] + (1-beta_l) * I, fp16 -----
__global__ void k_wfold(const float* __restrict__ W) {
    int l = blockIdx.y;
    float beta = logf(1.0f / (float)(l + 1) + 1.0f);
    int idx = blockIdx.x * blockDim.x + threadIdx.x;   // 0 .. 16383
    int k = idx >> 7, n = idx & 127;
    float v = beta * W[(size_t)l * DD * DD + idx];
    if (k == n) v += 1.0f - beta;
    g_w16[l][idx] = __float2half_rn(v);
}

// ---------------- scan stage 1: per-block (128 elems) partial sums ----------------
__global__ void __launch_bounds__(128) k_scan1() {
    int g = blockIdx.y;
    __shared__ int wsum[4];
    int t = threadIdx.x;
    int i = blockIdx.x * 128 + t;
    int v = (i < NN) ? g_deg[g][i] : 0;
    int x = v;
    for (int o = 16; o > 0; o >>= 1) x += __shfl_down_sync(0xffffffffu, x, o);
    if ((t & 31) == 0) wsum[t >> 5] = x;
    __syncthreads();
    if (t == 0) g_part[g][blockIdx.x] = wsum[0] + wsum[1] + wsum[2] + wsum[3];
}

// ---------------- scan stage 2: exclusive scan of NPART partials (1 block/graph) -
__global__ void __launch_bounds__(1024) k_scan2() {
    int g = blockIdx.y;
    __shared__ int sm[1024];
    int t = threadIdx.x;
    sm[t] = (t < NPART) ? g_part[g][t] : 0;
    __syncthreads();
    for (int off = 1; off < 1024; off <<= 1) {
        int v = sm[t];
        int add = (t >= off) ? sm[t - off] : 0;
        __syncthreads();
        sm[t] = v + add;
        __syncthreads();
    }
    if (t < NPART) g_part[g][t] = (t == 0) ? 0 : sm[t - 1];
    if (t == 0) g_rowptr[g][NN] = sm[NPART - 1];
}

// ---------------- scan stage 3: block-local scan + offset; also compute norm -----
__global__ void __launch_bounds__(128) k_scan3() {
    int g = blockIdx.y;
    __shared__ int wsum[4], woff[4];
    int t = threadIdx.x;
    int lane = t & 31, wid = t >> 5;
    int i = blockIdx.x * 128 + t;
    int v = (i < NN) ? g_deg[g][i] : 0;
    int x = v;
    for (int o = 1; o < 32; o <<= 1) {
        int y = __shfl_up_sync(0xffffffffu, x, o);
        if (lane >= o) x += y;
    }
    if (lane == 31) wsum[wid] = x;
    __syncthreads();
    if (t == 0) {
        int r = 0;
        for (int k = 0; k < 4; k++) { woff[k] = r; r += wsum[k]; }
    }
    __syncthreads();
    int excl = x - v + woff[wid] + g_part[g][blockIdx.x];
    if (i < NN) {
        g_rowptr[g][i] = excl;
        g_cursor[g][i] = excl;
        g_norm[g][i] = rsqrtf(fmaxf((float)v, 1.f));
    }
}

// ---------------- CSR fill: col grouped by dst (both graphs) ----------------
__global__ void k_fill(const int* __restrict__ src0, const int* __restrict__ dst0,
                       const int* __restrict__ src1, const int* __restrict__ dst1, int E) {
    int g = blockIdx.y;
    const int* src = g ? src1 : src0;
    const int* dst = g ? dst1 : dst0;
    int i = blockIdx.x * blockDim.x + threadIdx.x;
    if (i < E) {
        int pos = atomicAdd(&g_cursor[g][dst[i]], 1);
        g_col[g][pos] = src[i];
    }
}

// ---------------- gather helpers ----------------
__device__ __forceinline__ void acc_edge(float4& acc, const uint2* feat8, int s,
                                         float c, int lane) {
    uint2 u = feat8[(size_t)s * 32 + lane];
    float2 a = __half22float2(*reinterpret_cast<__half2*>(&u.x));
    float2 b = __half22float2(*reinterpret_cast<__half2*>(&u.y));
    acc.x += a.x * c;
    acc.y += a.y * c;
    acc.z += b.x * c;
    acc.w += b.y * c;
}

// ---------------- fused gather(fp16) + wmma GEMM layer, both graphs ---------------
// h = 0.9*agg*norm + 0.1*feat0(fp16); out = relu(h @ W' + bias); W' identity-folded.
// Layer 3 additionally accumulates column stats.
__global__ void __launch_bounds__(256) k_layer(const __half* __restrict__ s16_0,
                                               const __half* __restrict__ s16_1,
                                               __half* __restrict__ dh0,
                                               __half* __restrict__ dh1,
                                               float* __restrict__ df0,
                                               float* __restrict__ df1,
                                               const __half* __restrict__ f016_0,
                                               const __half* __restrict__ f016_1,
                                               const __half* __restrict__ Wf,
                                               const float* __restrict__ bias,
                                               int is_last) {
    __shared__ __align__(16) unsigned char smem_raw[64 * DD * 4];  // 32 KB
    __half* hs16 = reinterpret_cast<__half*>(smem_raw);            // [64][128] fp16
    float* outs = reinterpret_cast<float*>(smem_raw);              // [64][128] fp32

    int g = blockIdx.y;
    const uint2* feat8 = reinterpret_cast<const uint2*>(g ? s16_1 : s16_0);
    const uint2* f016 = reinterpret_cast<const uint2*>(g ? f016_1 : f016_0);
    __half* dsth = g ? dh1 : dh0;
    float* dstf = g ? df1 : df0;

    int row0 = blockIdx.x * 64;
    int tid = threadIdx.x;
    int w = tid >> 5, lane = tid & 31;

    const int* __restrict__ rp = g_rowptr[g];
    const int* __restrict__ col = g_col[g];
    const float* __restrict__ nrm = g_norm[g];

    // ---- gather phase: warp w handles rows [8w, 8w+8) as 4 interleaved pairs ----
    for (int pr = 0; pr < 4; pr++) {
        int rA = w * 8 + pr * 2;
        int rB = rA + 1;
        int nA = row0 + rA, nB = row0 + rB;
        float4 aA = make_float4(0.f, 0.f, 0.f, 0.f);
        float4 aB = make_float4(0.f, 0.f, 0.f, 0.f);
        int eA = 0, endA = 0, eB = 0, endB = 0;
        if (nA < NN) { eA = __ldg(&rp[nA]); endA = __ldg(&rp[nA + 1]); }
        if (nB < NN) { eB = __ldg(&rp[nB]); endB = __ldg(&rp[nB + 1]); }

        while (eA + 1 < endA && eB + 1 < endB) {
            int sA0 = __ldg(&col[eA]);
            int sA1 = __ldg(&col[eA + 1]);
            int sB0 = __ldg(&col[eB]);
            int sB1 = __ldg(&col[eB + 1]);
            float cA0 = __ldg(&nrm[sA0]);
            float cA1 = __ldg(&nrm[sA1]);
            float cB0 = __ldg(&nrm[sB0]);
            float cB1 = __ldg(&nrm[sB1]);
            acc_edge(aA, feat8, sA0, cA0, lane);
            acc_edge(aA, feat8, sA1, cA1, lane);
            acc_edge(aB, feat8, sB0, cB0, lane);
            acc_edge(aB, feat8, sB1, cB1, lane);
            eA += 2; eB += 2;
        }
        for (; eA + 1 < endA; eA += 2) {
            int s0 = __ldg(&col[eA]);
            int s1 = __ldg(&col[eA + 1]);
            float c0 = __ldg(&nrm[s0]);
            float c1 = __ldg(&nrm[s1]);
            acc_edge(aA, feat8, s0, c0, lane);
            acc_edge(aA, feat8, s1, c1, lane);
        }
        if (eA < endA) {
            int s0 = __ldg(&col[eA]);
            acc_edge(aA, feat8, s0, __ldg(&nrm[s0]), lane);
        }
        for (; eB + 1 < endB; eB += 2) {
            int s0 = __ldg(&col[eB]);
            int s1 = __ldg(&col[eB + 1]);
            float c0 = __ldg(&nrm[s0]);
            float c1 = __ldg(&nrm[s1]);
            acc_edge(aB, feat8, s0, c0, lane);
            acc_edge(aB, feat8, s1, c1, lane);
        }
        if (eB < endB) {
            int s0 = __ldg(&col[eB]);
            acc_edge(aB, feat8, s0, __ldg(&nrm[s0]), lane);
        }

        // residual (fp16 feat0) + store h as fp16
        if (nA < NN) {
            float nr = nrm[nA];
            uint2 u = f016[(size_t)nA * 32 + lane];
            float2 fa = __half22float2(*reinterpret_cast<__half2*>(&u.x));
            float2 fb = __half22float2(*reinterpret_cast<__half2*>(&u.y));
            aA.x = 0.9f * aA.x * nr + 0.1f * fa.x;
            aA.y = 0.9f * aA.y * nr + 0.1f * fa.y;
            aA.z = 0.9f * aA.z * nr + 0.1f * fb.x;
            aA.w = 0.9f * aA.w * nr + 0.1f * fb.y;
        }
        if (nB < NN) {
            float nr = nrm[nB];
            uint2 u = f016[(size_t)nB * 32 + lane];
            float2 fa = __half22float2(*reinterpret_cast<__half2*>(&u.x));
            float2 fb = __half22float2(*reinterpret_cast<__half2*>(&u.y));
            aB.x = 0.9f * aB.x * nr + 0.1f * fa.x;
            aB.y = 0.9f * aB.y * nr + 0.1f * fa.y;
            aB.z = 0.9f * aB.z * nr + 0.1f * fb.x;
            aB.w = 0.9f * aB.w * nr + 0.1f * fb.y;
        }
        {
            __half2 lo = __floats2half2_rn(aA.x, aA.y);
            __half2 hi = __floats2half2_rn(aA.z, aA.w);
            uint2 o;
            o.x = *reinterpret_cast<unsigned*>(&lo);
            o.y = *reinterpret_cast<unsigned*>(&hi);
            reinterpret_cast<uint2*>(&hs16[rA * DD])[lane] = o;
            lo = __floats2half2_rn(aB.x, aB.y);
            hi = __floats2half2_rn(aB.z, aB.w);
            o.x = *reinterpret_cast<unsigned*>(&lo);
            o.y = *reinterpret_cast<unsigned*>(&hi);
            reinterpret_cast<uint2*>(&hs16[rB * DD])[lane] = o;
        }
    }
    __syncthreads();

    // ---- wmma phase: warp w -> row tile (w>>1)*16, col half (w&1)*64 ----
    {
        int rt = w >> 1;
        int ch = w & 1;
        wmma::fragment<wmma::accumulator, 16, 16, 16, float> fc[4];
#pragma unroll
        for (int ct = 0; ct < 4; ct++) wmma::fill_fragment(fc[ct], 0.f);

#pragma unroll
        for (int k0 = 0; k0 < 8; k0++) {
            wmma::fragment<wmma::matrix_a, 16, 16, 16, __half, wmma::row_major> fa;
            wmma::load_matrix_sync(fa, &hs16[(rt * 16) * DD + k0 * 16], DD);
#pragma unroll
            for (int ct = 0; ct < 4; ct++) {
                wmma::fragment<wmma::matrix_b, 16, 16, 16, __half, wmma::row_major> fb;
                wmma::load_matrix_sync(fb, &Wf[(k0 * 16) * DD + ch * 64 + ct * 16], DD);
                wmma::mma_sync(fc[ct], fa, fb, fc[ct]);
            }
        }
        __syncthreads();   // all frag_a loads done; safe to overwrite smem as fp32
#pragma unroll
        for (int ct = 0; ct < 4; ct++)
            wmma::store_matrix_sync(&outs[(rt * 16) * DD + ch * 64 + ct * 16], fc[ct],
                                    DD, wmma::mem_row_major);
    }
    __syncthreads();

    // ---- epilogue: o = relu(outs + bias); column pairs (2*lane + 64j) ----
    float csum[4] = {0.f, 0.f, 0.f, 0.f};
    float csq[4] = {0.f, 0.f, 0.f, 0.f};
#pragma unroll
    for (int r8 = 0; r8 < 8; r8++) {
        int r = w * 8 + r8;
        int n = row0 + r;
        if (n >= NN) continue;
#pragma unroll
        for (int j = 0; j < 2; j++) {
            int c = 2 * lane + 64 * j;
            float o0 = outs[r * DD + c] + __ldg(&bias[c]);
            float o1 = outs[r * DD + c + 1] + __ldg(&bias[c + 1]);
            o0 = fmaxf(o0, 0.f);
            o1 = fmaxf(o1, 0.f);
            if (is_last) {
                dstf[(size_t)n * DD + c] = o0;
                dstf[(size_t)n * DD + c + 1] = o1;
                csum[2 * j] += o0;  csq[2 * j] += o0 * o0;
                csum[2 * j + 1] += o1;  csq[2 * j + 1] += o1 * o1;
            } else {
                __half2 h2 = __floats2half2_rn(o0, o1);
                *reinterpret_cast<__half2*>(&dsth[(size_t)n * DD + c]) = h2;
            }
        }
    }

    if (is_last) {
        __syncthreads();
        float* red = outs; // reuse as [16][128]: rows 0-7 sum, 8-15 sumsq
#pragma unroll
        for (int j = 0; j < 2; j++) {
            red[w * DD + 2 * lane + 64 * j] = csum[2 * j];
            red[w * DD + 2 * lane + 64 * j + 1] = csum[2 * j + 1];
            red[(8 + w) * DD + 2 * lane + 64 * j] = csq[2 * j];
            red[(8 + w) * DD + 2 * lane + 64 * j + 1] = csq[2 * j + 1];
        }
        __syncthreads();
        int c = tid & 127;
        int which = tid >> 7;
        float tot = 0.f;
#pragma unroll
        for (int w2 = 0; w2 < 8; w2++) tot += red[(which * 8 + w2) * DD + c];
        if (which == 0) atomicAdd(&g_sum[g][c], (double)tot);
        else            atomicAdd(&g_sumsq[g][c], (double)tot);
    }
}

__global__ void k_finalize() {
    int g = blockIdx.y;
    int c = threadIdx.x;
    if (c < DD) {
        double mean = g_sum[g][c] / (double)NN;
        double var = (g_sumsq[g][c] - (double)NN * mean * mean) / (double)(NN - 1);
        if (var < 0.0) var = 0.0;
        float sd = (float)sqrt(var);
        g_mean[g][c] = (float)mean;
        g_inv[g][c] = 1.f / fmaxf(sd, 1e-12f);
    }
}

__global__ void k_write(const float* __restrict__ feat0, const float* __restrict__ feat1,
                        float* __restrict__ out) {
    int g = blockIdx.y;
    const float* feat = g ? feat1 : feat0;
    float* o = out + (size_t)g * ND;
    int idx = blockIdx.x * blockDim.x + threadIdx.x;
    int stride = gridDim.x * blockDim.x;
    for (int i = idx; i < ND; i += stride) {
        int c = i & 127;
        o[i] = (feat[i] - g_mean[g][c]) * g_inv[g][c];
    }
}

// ---------------- launch (single stream — capture-safe) ----------------
extern "C" void kernel_launch(void* const* d_in, const int* in_sizes, int n_in,
                              void* d_out, int out_size) {
    const float* feat0 = (const float*)d_in[0];
    const float* feat1 = (const float*)d_in[1];
    const int* src0 = (const int*)d_in[2];
    const int* dst0 = (const int*)d_in[3];
    const int* src1 = (const int*)d_in[4];
    const int* dst1 = (const int*)d_in[5];
    const float* weights = (const float*)d_in[6];
    const float* biases = (const float*)d_in[7];
    int E = in_sizes[2];
    float* out = (float*)d_out;

    static __half* h16_addr[2][3] = {{nullptr, nullptr, nullptr},
                                     {nullptr, nullptr, nullptr}};
    static float* fin_addr[2] = {nullptr, nullptr};
    static __half* w16_addr = nullptr;
    if (!h16_addr[0][0]) {
        void* p = nullptr;
        cudaGetSymbolAddress(&p, g_h16);
        __half* hbase = (__half*)p;
        for (int g = 0; g < 2; g++)
            for (int b = 0; b < 3; b++)
                h16_addr[g][b] = hbase + ((size_t)g * 3 + b) * (size_t)ND;
        cudaGetSymbolAddress(&p, g_fin);
        float* fbase = (float*)p;
        for (int g = 0; g < 2; g++) fin_addr[g] = fbase + (size_t)g * ND;
        cudaGetSymbolAddress(&p, g_w16);
        w16_addr = (__half*)p;
    }

    int eb = (E + 255) / 256;
    int layer_blocks = (NN + 63) / 64;

    k_init<<<dim3(256, 2), 256>>>();
    k_count<<<dim3(eb, 2), 256>>>(dst0, dst1, E);
    k_tofp16<<<dim3(1024, 2), 256>>>(feat0, feat1);
    k_wfold<<<dim3(64, 4), 256>>>(weights);
    k_scan1<<<dim3(NPART, 2), 128>>>();
    k_scan2<<<dim3(1, 2), 1024>>>();
    k_scan3<<<dim3(NPART, 2), 128>>>();
    k_fill<<<dim3(eb, 2), 256>>>(src0, dst0, src1, dst1, E);

    // buf0 = fp16(feat0), persistent (residual source).
    // layer l: src = sbuf[l], dst = dbuf[l] (fp16 for 0-2, g_fin fp32 for 3)
    const int sbuf[4] = {0, 1, 2, 1};
    const int dbuf[4] = {1, 2, 1, 0 /*unused*/};
    for (int l = 0; l < 4; l++) {
        int is_last = (l == 3) ? 1 : 0;
        const __half* s0 = h16_addr[0][sbuf[l]];
        const __half* s1 = h16_addr[1][sbuf[l]];
        __half* dh0 = h16_addr[0][dbuf[l]];
        __half* dh1 = h16_addr[1][dbuf[l]];
        k_layer<<<dim3(layer_blocks, 2), 256>>>(s0, s1, dh0, dh1,
                                                fin_addr[0], fin_addr[1],
                                                h16_addr[0][0], h16_addr[1][0],
                                                w16_addr + (size_t)l * DD * DD,
                                                biases + (size_t)l * DD, is_last);
    }

    k_finalize<<<dim3(1, 2), DD>>>();
    k_write<<<dim3(1024, 2), 256>>>(fin_addr[0], fin_addr[1], out);
}